// round 11
// baseline (speedup 1.0000x reference)
#include <cuda_runtime.h>
#include <cuda_fp16.h>
#include <math.h>
#include <float.h>
#include <stdint.h>

// Problem constants
#define GH   16        // B*H groups
#define SEQ  2048
#define EMB  512
#define DH   64
#define MR   4096      // B*S rows
#define MLPD 2048

typedef unsigned long long u64;

// ---------------- scratch (static device globals; no allocation) ----------------
__device__ float  g_nq [MR*EMB];
__device__ float  g_q  [MR*EMB];
__device__ float  g_k  [MR*EMB];
__device__ float  g_v  [MR*EMB];
__device__ float  g_W  [(size_t)GH*SEQ*SEQ];     // 256MB raw gated scores (fp32)
__device__ __half g_P  [(size_t)GH*SEQ*SEQ];     // 128MB exp'd (un-normalized) probs
__device__ float  g_rsum[GH*SEQ];
__device__ float  g_rmax[GH*SEQ];
__device__ float  g_rmin[GH*SEQ];
__device__ float  g_Z  [GH*SEQ];
__device__ float  g_Oc [MR*EMB];
__device__ float  g_x  [MR*EMB];
__device__ float  g_h  [MR*EMB];
__device__ float  g_mlp[(size_t)MR*MLPD];

// ---------------- misc helpers ----------------
__device__ __forceinline__ void atomicMaxF(float* addr, float val) {
    int old = __float_as_int(*addr);
    while (__int_as_float(old) < val) {
        int assumed = old;
        old = atomicCAS((int*)addr, assumed, __float_as_int(val));
        if (old == assumed) break;
    }
}
__device__ __forceinline__ void atomicMinF(float* addr, float val) {
    int old = __float_as_int(*addr);
    while (__int_as_float(old) > val) {
        int assumed = old;
        old = atomicCAS((int*)addr, assumed, __float_as_int(val));
        if (old == assumed) break;
    }
}

// ---------------- tf32 / mma helpers ----------------
__device__ __forceinline__ float tf32r(float x) {
    uint32_t r; asm("cvt.rna.tf32.f32 %0, %1;" : "=r"(r) : "f"(x));
    return __uint_as_float(r);
}
__device__ __forceinline__ void mma8(float* c, const uint32_t* a, const uint32_t* b) {
    asm volatile(
        "mma.sync.aligned.m16n8k8.row.col.f32.tf32.tf32.f32 "
        "{%0,%1,%2,%3}, {%4,%5,%6,%7}, {%8,%9}, {%0,%1,%2,%3};"
        : "+f"(c[0]), "+f"(c[1]), "+f"(c[2]), "+f"(c[3])
        : "r"(a[0]), "r"(a[1]), "r"(a[2]), "r"(a[3]), "r"(b[0]), "r"(b[1]));
}
__device__ __forceinline__ void mma16h(float* c, const uint32_t* a, const uint32_t* b) {
    asm volatile(
        "mma.sync.aligned.m16n8k16.row.col.f32.f16.f16.f32 "
        "{%0,%1,%2,%3}, {%4,%5,%6,%7}, {%8,%9}, {%0,%1,%2,%3};"
        : "+f"(c[0]), "+f"(c[1]), "+f"(c[2]), "+f"(c[3])
        : "r"(a[0]), "r"(a[1]), "r"(a[2]), "r"(a[3]), "r"(b[0]), "r"(b[1]));
}

// ======== ROUND-4/6 dense GEMM (validated): C[m,n]=sum_k A[m,k]B[n,k]+bias ========
#define MM_PAD   36
#define MM_ARR   (128 * MM_PAD)
#define MM_SMEM  (4 * MM_ARR * 4)                  // 73728 B

template <int EPI>
__global__ __launch_bounds__(256, 2)
void sgemm_mma(const float* __restrict__ A, const float* __restrict__ B,
               const float* __restrict__ bias, const float* __restrict__ res,
               float* __restrict__ C0, float* __restrict__ C1, float* __restrict__ C2,
               int N, int K) {
    extern __shared__ float sm[];
    float* sAh = sm;
    float* sAl = sm + 1 * MM_ARR;
    float* sBh = sm + 2 * MM_ARR;
    float* sBl = sm + 3 * MM_ARR;

    const int tid = threadIdx.x;
    const int wid = tid >> 5, lid = tid & 31;
    const int g = lid >> 2, t4 = lid & 3;
    const int wm = (wid >> 2) << 6;
    const int wn = (wid & 3) << 5;
    const int m0 = blockIdx.y << 7, n0 = blockIdx.x << 7;
    const int nc = K >> 5;

    const int lrow = tid >> 1;
    const int lkb  = (tid & 1) << 4;
    const float* Arow = A + (size_t)(m0 + lrow) * K + lkb;
    const float* Brow = B + (size_t)(n0 + lrow) * K + lkb;

    float4 ra[4], rb[4];
    auto load_regs = [&](int c) {
        const int kc = c << 5;
#pragma unroll
        for (int i = 0; i < 4; i++) {
            ra[i] = *(const float4*)(Arow + kc + (i << 2));
            rb[i] = *(const float4*)(Brow + kc + (i << 2));
        }
    };
    auto store_smem = [&]() {
        const int base = lrow * MM_PAD + lkb;
#pragma unroll
        for (int i = 0; i < 4; i++) {
            float4 a = ra[i], b = rb[i];
            float4 ah, al, bh, bl;
            ah.x = tf32r(a.x); al.x = tf32r(a.x - ah.x);
            ah.y = tf32r(a.y); al.y = tf32r(a.y - ah.y);
            ah.z = tf32r(a.z); al.z = tf32r(a.z - ah.z);
            ah.w = tf32r(a.w); al.w = tf32r(a.w - ah.w);
            bh.x = tf32r(b.x); bl.x = tf32r(b.x - bh.x);
            bh.y = tf32r(b.y); bl.y = tf32r(b.y - bh.y);
            bh.z = tf32r(b.z); bl.z = tf32r(b.z - bh.z);
            bh.w = tf32r(b.w); bl.w = tf32r(b.w - bh.w);
            *(float4*)&sAh[base + (i << 2)] = ah;
            *(float4*)&sAl[base + (i << 2)] = al;
            *(float4*)&sBh[base + (i << 2)] = bh;
            *(float4*)&sBl[base + (i << 2)] = bl;
        }
    };

    float acc[4][4][4];
#pragma unroll
    for (int mi = 0; mi < 4; mi++)
#pragma unroll
        for (int ni = 0; ni < 4; ni++)
#pragma unroll
            for (int f = 0; f < 4; f++) acc[mi][ni][f] = 0.f;

    load_regs(0);
    store_smem();
    __syncthreads();

    for (int c = 0; c < nc; c++) {
        if (c + 1 < nc) load_regs(c + 1);
#pragma unroll
        for (int ki = 0; ki < 4; ki++) {
            const int kc = (ki << 3) + t4;
            uint32_t bh[4][2], bl[4][2];
#pragma unroll
            for (int ni = 0; ni < 4; ni++) {
                const int nn = (wn + (ni << 3) + g) * MM_PAD;
                bh[ni][0] = __float_as_uint(sBh[nn + kc]);
                bh[ni][1] = __float_as_uint(sBh[nn + kc + 4]);
                bl[ni][0] = __float_as_uint(sBl[nn + kc]);
                bl[ni][1] = __float_as_uint(sBl[nn + kc + 4]);
            }
#pragma unroll
            for (int mi = 0; mi < 4; mi++) {
                const int r0 = (wm + (mi << 4) + g) * MM_PAD;
                const int r8 = r0 + (MM_PAD << 3);
                uint32_t ah[4], al[4];
                ah[0] = __float_as_uint(sAh[r0 + kc]);
                ah[1] = __float_as_uint(sAh[r8 + kc]);
                ah[2] = __float_as_uint(sAh[r0 + kc + 4]);
                ah[3] = __float_as_uint(sAh[r8 + kc + 4]);
                al[0] = __float_as_uint(sAl[r0 + kc]);
                al[1] = __float_as_uint(sAl[r8 + kc]);
                al[2] = __float_as_uint(sAl[r0 + kc + 4]);
                al[3] = __float_as_uint(sAl[r8 + kc + 4]);
#pragma unroll
                for (int ni = 0; ni < 4; ni++) {
                    mma8(acc[mi][ni], ah, bh[ni]);
                    mma8(acc[mi][ni], ah, bl[ni]);
                    mma8(acc[mi][ni], al, bh[ni]);
                }
            }
        }
        __syncthreads();
        if (c + 1 < nc) {
            store_smem();
            __syncthreads();
        }
    }

    auto epi2 = [&](int row, int col, float v0, float v1) {
        v0 += bias[col]; v1 += bias[col + 1];
        if (EPI == 0) {
            float* dst = (col < 512) ? C0 : ((col < 1024) ? C1 : C2);
            *(float2*)&dst[(size_t)row * 512 + (col & 511)] = make_float2(v0, v1);
        } else if (EPI == 1) {
            float2 rv = *(const float2*)&res[(size_t)row * N + col];
            *(float2*)&C0[(size_t)row * N + col] = make_float2(v0 + rv.x, v1 + rv.y);
        } else {
            float2 o;
            o.x = 0.5f * v0 * (1.f + erff(v0 * 0.7071067811865475f));
            o.y = 0.5f * v1 * (1.f + erff(v1 * 0.7071067811865475f));
            *(float2*)&C0[(size_t)row * N + col] = o;
        }
    };
#pragma unroll
    for (int mi = 0; mi < 4; mi++) {
        const int r = m0 + wm + (mi << 4) + g;
#pragma unroll
        for (int ni = 0; ni < 4; ni++) {
            const int cn = n0 + wn + (ni << 3) + (t4 << 1);
            epi2(r,     cn, acc[mi][ni][0], acc[mi][ni][1]);
            epi2(r + 8, cn, acc[mi][ni][2], acc[mi][ni][3]);
        }
    }
}

// ======== scores: mainloop as round-6; NEW coalesced epilogue w/ deferred reduce ====
#define PR        36
#define MAT_PAIRS (128 * PR)
#define SC_SMEM   (2 * MAT_PAIRS * 8)   // 73728 bytes
#define ST_PAD    132                    // float4-aligned staging rows (128*132*4=67584)

__device__ __forceinline__ void split_store(float2* dst, int basep, const float4* r) {
#pragma unroll
    for (int i = 0; i < 4; i++) {
        float4 v = r[i];
        float h0 = tf32r(v.x), h1 = tf32r(v.y), h2 = tf32r(v.z), h3 = tf32r(v.w);
        float l0 = tf32r(v.x - h0), l1 = tf32r(v.y - h1);
        float l2 = tf32r(v.z - h2), l3 = tf32r(v.w - h3);
        *(float4*)(dst + basep + (i << 2))     = make_float4(h0, l0, h1, l1);
        *(float4*)(dst + basep + (i << 2) + 2) = make_float4(h2, l2, h3, l3);
    }
}

__device__ __forceinline__ void mma_chunk_tf32(const float2* sA2, const float2* sB2,
                                               int wm, int wn, int gq, int t4,
                                               float (&acc)[4][4][4]) {
#pragma unroll
    for (int ki = 0; ki < 4; ki++) {
        const int kc = (ki << 3) + t4;
        uint32_t bh[4][2], bl[4][2];
#pragma unroll
        for (int ni = 0; ni < 4; ni++) {
            const int nn = (wn + (ni << 3) + gq) * PR;
            float2 b0 = sB2[nn + kc];
            float2 b1 = sB2[nn + kc + 4];
            bh[ni][0] = __float_as_uint(b0.x); bh[ni][1] = __float_as_uint(b1.x);
            bl[ni][0] = __float_as_uint(b0.y); bl[ni][1] = __float_as_uint(b1.y);
        }
#pragma unroll
        for (int mi = 0; mi < 4; mi++) {
            const int r0 = (wm + (mi << 4) + gq) * PR, r8 = r0 + (PR << 3);
            float2 a00 = sA2[r0 + kc], a01 = sA2[r0 + kc + 4];
            float2 a10 = sA2[r8 + kc], a11 = sA2[r8 + kc + 4];
            uint32_t ah[4] = { __float_as_uint(a00.x), __float_as_uint(a10.x),
                               __float_as_uint(a01.x), __float_as_uint(a11.x) };
            uint32_t al[4] = { __float_as_uint(a00.y), __float_as_uint(a10.y),
                               __float_as_uint(a01.y), __float_as_uint(a11.y) };
#pragma unroll
            for (int ni = 0; ni < 4; ni++) {
                mma8(acc[mi][ni], ah, bh[ni]);
                mma8(acc[mi][ni], ah, bl[ni]);
                mma8(acc[mi][ni], al, bh[ni]);
            }
        }
    }
}

__global__ __launch_bounds__(256, 2)
void scores_mma(const float* __restrict__ Q, const float* __restrict__ Km,
                const float* __restrict__ gate, float* __restrict__ W,
                float* __restrict__ rsum, float* __restrict__ rmaxp,
                float* __restrict__ rminp) {
    extern __shared__ float2 s2[];
    float2* sA2 = s2;
    float2* sB2 = s2 + MAT_PAIRS;

    const int g = blockIdx.z;
    const int tid = threadIdx.x;
    const int wid = tid >> 5, lid = tid & 31;
    const int gq = lid >> 2, t4 = lid & 3;
    const int wm = (wid >> 2) << 6;
    const int wn = (wid & 3) << 5;
    const int i0 = blockIdx.y << 7, j0 = blockIdx.x << 7;

    const int lrow = tid >> 1;
    const int lkb  = (tid & 1) << 4;
    const int basep = lrow * PR + lkb;
    const float* Arow = Q + (size_t)g * SEQ * DH + (size_t)(i0 + lrow) * DH + lkb;
    const float* Brow = Km + (size_t)g * SEQ * DH + (size_t)(j0 + lrow) * DH + lkb;

    float acc[4][4][4];
#pragma unroll
    for (int mi = 0; mi < 4; mi++)
#pragma unroll
        for (int ni = 0; ni < 4; ni++)
#pragma unroll
            for (int f = 0; f < 4; f++) acc[mi][ni][f] = 0.f;

#pragma unroll
    for (int c = 0; c < 2; c++) {
        float4 ra[4], rb[4];
        const int kc = c << 5;
#pragma unroll
        for (int i = 0; i < 4; i++) {
            ra[i] = *(const float4*)(Arow + kc + (i << 2));
            rb[i] = *(const float4*)(Brow + kc + (i << 2));
        }
        if (c) __syncthreads();
        split_store(sA2, basep, ra);
        split_store(sB2, basep, rb);
        __syncthreads();
        mma_chunk_tf32(sA2, sB2, wm, wn, gq, t4, acc);
    }

    // ---- stage acc tile to smem (float2 stores, float4-aligned pad) ----
    __syncthreads();
    float* st = (float*)s2;            // [128][ST_PAD]
#pragma unroll
    for (int mi = 0; mi < 4; mi++) {
#pragma unroll
        for (int half = 0; half < 2; half++) {
            const int row = wm + (mi << 4) + gq + (half << 3);
#pragma unroll
            for (int ni = 0; ni < 4; ni++) {
                const int col = wn + (ni << 3) + (t4 << 1);
                *(float2*)&st[row * ST_PAD + col] =
                    make_float2(acc[mi][ni][half * 2 + 0], acc[mi][ni][half * 2 + 1]);
            }
        }
    }
    __syncthreads();

    // ---- coalesced streaming epilogue: 8-row batches, deferred reduction ----
    const size_t wb = (size_t)g * SEQ * SEQ;
#pragma unroll
    for (int batch = 0; batch < 2; batch++) {
        float rs[8], rmx[8], rmn[8];
        // streaming phase: 8 independent rows -> MLP high, pure LDG/LDS/STG
#pragma unroll
        for (int j = 0; j < 8; j++) {
            const int row = (wid << 4) + (batch << 3) + j;
            const size_t off = wb + (size_t)(i0 + row) * SEQ + j0 + (lid << 2);
            float4 a = *(const float4*)&st[row * ST_PAD + (lid << 2)];
            float4 gt = *(const float4*)&gate[off];
            float4 v;
            v.x = a.x * gt.x; v.y = a.y * gt.y; v.z = a.z * gt.z; v.w = a.w * gt.w;
            *(float4*)&W[off] = v;
            rs[j]  = (v.x + v.y) + (v.z + v.w);
            rmx[j] = fmaxf(fmaxf(v.x, v.y), fmaxf(v.z, v.w));
            rmn[j] = fminf(fminf(v.x, v.y), fminf(v.z, v.w));
        }
        // reduction phase: no memory ops, just shfls
#pragma unroll
        for (int o = 16; o; o >>= 1) {
#pragma unroll
            for (int j = 0; j < 8; j++) {
                rs[j]  += __shfl_xor_sync(~0u, rs[j], o);
                rmx[j] = fmaxf(rmx[j], __shfl_xor_sync(~0u, rmx[j], o));
                rmn[j] = fminf(rmn[j], __shfl_xor_sync(~0u, rmn[j], o));
            }
        }
        if (lid < 8) {
            // lane j commits row j's stats (values uniform across warp post-reduce)
            const int row = (wid << 4) + (batch << 3) + lid;
            const int r = g * SEQ + i0 + row;
            atomicAdd(&rsum[r], rs[lid]);
            atomicMaxF(&rmaxp[r], rmx[lid]);
            atomicMinF(&rminp[r], rmn[lid]);
        }
    }
}

__global__ void init_stats(float* rsum, float* rmax, float* rmin) {
    int i = blockIdx.x * blockDim.x + threadIdx.x;
    if (i < GH * SEQ) { rsum[i] = 0.f; rmax[i] = -FLT_MAX; rmin[i] = FLT_MAX; }
}

// ---------------- LayerNorm (1 block / row of 512) ----------------
__global__ void ln_kernel(const float* __restrict__ x, const float* __restrict__ w,
                          const float* __restrict__ b, float* __restrict__ y) {
    int row = blockIdx.x;
    const float* xr = x + (size_t)row * EMB;
    int t = threadIdx.x;
    float v0 = xr[t], v1 = xr[t + 256];
    float s = v0 + v1, q = v0 * v0 + v1 * v1;
#pragma unroll
    for (int off = 16; off; off >>= 1) {
        s += __shfl_xor_sync(~0u, s, off);
        q += __shfl_xor_sync(~0u, q, off);
    }
    __shared__ float ss[8], sq[8];
    if ((t & 31) == 0) { ss[t >> 5] = s; sq[t >> 5] = q; }
    __syncthreads();
    if (t == 0) {
        float s2 = 0.f, q2 = 0.f;
#pragma unroll
        for (int i = 0; i < 8; i++) { s2 += ss[i]; q2 += sq[i]; }
        ss[0] = s2; sq[0] = q2;
    }
    __syncthreads();
    float mean = ss[0] * (1.f / EMB);
    float var  = sq[0] * (1.f / EMB) - mean * mean;
    float rstd = rsqrtf(var + 1e-5f);
    float* yr = y + (size_t)row * EMB;
    yr[t]       = (v0 - mean) * rstd * w[t]       + b[t];
    yr[t + 256] = (v1 - mean) * rstd * w[t + 256] + b[t + 256];
}

// ======== fused: exp -> P fp16, Z, head-averaged attn weights (round-10) ========
#define AW_SMEM (8 * SEQ * 2)   // 32768 bytes of half
__global__ void sfmax_avg(const float* __restrict__ W, const float* __restrict__ rsum,
                          const float* __restrict__ rmaxp, const float* __restrict__ rminp,
                          __half* __restrict__ P, float* __restrict__ Z,
                          float* __restrict__ out) {
    extern __shared__ __half sph[];     // [8][2048] half
    __shared__ float sz[8];
    const int i = blockIdx.x, b = blockIdx.y;
    const int tid = threadIdx.x;
    if (tid < 8) sz[tid] = 0.f;
    __syncthreads();

    float inv[8], mh[8], z[8];
    int rowh[8];
#pragma unroll
    for (int h = 0; h < 8; h++) {
        rowh[h] = (b * 8 + h) * SEQ + i;
        float s = rsum[rowh[h]] + 1e-12f;
        inv[h] = 1.f / s;
        mh[h] = (s > 0.f) ? rmaxp[rowh[h]] * inv[h] : rminp[rowh[h]] * inv[h];
        z[h] = 0.f;
    }

#pragma unroll
    for (int k = 0; k < 2; k++) {
        const int j = (tid + (k << 8)) << 2;
        float4 w4[8];
#pragma unroll
        for (int h = 0; h < 8; h++)
            w4[h] = *(const float4*)&W[(size_t)rowh[h] * SEQ + j];
#pragma unroll
        for (int h = 0; h < 8; h++) {
            float4 p;
            p.x = __expf(fmaf(w4[h].x, inv[h], -mh[h]));
            p.y = __expf(fmaf(w4[h].y, inv[h], -mh[h]));
            p.z = __expf(fmaf(w4[h].z, inv[h], -mh[h]));
            p.w = __expf(fmaf(w4[h].w, inv[h], -mh[h]));
            __half2 h0 = __floats2half2_rn(p.x, p.y);
            __half2 h1 = __floats2half2_rn(p.z, p.w);
            uint2 pk = make_uint2(*(uint32_t*)&h0, *(uint32_t*)&h1);
            *(uint2*)&P[(size_t)rowh[h] * SEQ + j] = pk;
            *(uint2*)&sph[h * SEQ + j] = pk;
            z[h] += (p.x + p.y) + (p.z + p.w);
        }
    }
#pragma unroll
    for (int h = 0; h < 8; h++) {
#pragma unroll
        for (int off = 16; off; off >>= 1) z[h] += __shfl_xor_sync(~0u, z[h], off);
    }
    if ((tid & 31) == 0) {
#pragma unroll
        for (int h = 0; h < 8; h++) atomicAdd(&sz[h], z[h]);
    }
    __syncthreads();
    if (tid < 8) Z[(b * 8 + tid) * SEQ + i] = sz[tid];
    float iz[8];
#pragma unroll
    for (int h = 0; h < 8; h++) iz[h] = 0.125f / sz[h];
    float* orow = out + (size_t)b * SEQ * SEQ + (size_t)i * SEQ;
#pragma unroll
    for (int k = 0; k < 2; k++) {
        const int j = (tid + (k << 8)) << 2;
        float4 a = make_float4(0.f, 0.f, 0.f, 0.f);
#pragma unroll
        for (int h = 0; h < 8; h++) {
            uint2 pk = *(const uint2*)&sph[h * SEQ + j];
            float2 p01 = __half22float2(*(__half2*)&pk.x);
            float2 p23 = __half22float2(*(__half2*)&pk.y);
            a.x = fmaf(p01.x, iz[h], a.x);
            a.y = fmaf(p01.y, iz[h], a.y);
            a.z = fmaf(p23.x, iz[h], a.z);
            a.w = fmaf(p23.y, iz[h], a.w);
        }
        *(float4*)&orow[j] = a;
    }
}

// ======== PV via fp16 mma: Oc[(b,s),h*64+d] = (sum_k P[g,s,k] V[g,k,d]) / Z ========
#define PVS 40
__global__ __launch_bounds__(128, 4)
void pv_mma(const __half* __restrict__ P, const float* __restrict__ V,
            const float* __restrict__ Z, float* __restrict__ Oc) {
    __shared__ __half Ps[128 * PVS];
    __shared__ __half Vs[64 * PVS];
    const int g = blockIdx.y;
    const int m0 = blockIdx.x << 7;
    const int tid = threadIdx.x;
    const int wid = tid >> 5, lid = tid & 31;
    const int gq = lid >> 2, t4 = lid & 3;
    const int wm = wid << 5;

    const __half* Pg = P + (size_t)g * SEQ * SEQ;
    const float*  Vg = V + (size_t)g * SEQ * DH;

    float acc[2][8][4];
#pragma unroll
    for (int mi = 0; mi < 2; mi++)
#pragma unroll
        for (int ni = 0; ni < 8; ni++)
#pragma unroll
            for (int f = 0; f < 4; f++) acc[mi][ni][f] = 0.f;

    const int vk = tid >> 2;
    const int vc = (tid & 3) << 4;

    for (int k0 = 0; k0 < SEQ; k0 += 32) {
        const __half* prow = Pg + (size_t)(m0 + tid) * SEQ + k0;
        float4 p0 = *(const float4*)(prow + 0);
        float4 p1 = *(const float4*)(prow + 8);
        float4 p2 = *(const float4*)(prow + 16);
        float4 p3 = *(const float4*)(prow + 24);
        float4 v4[4];
#pragma unroll
        for (int i = 0; i < 4; i++)
            v4[i] = *(const float4*)&Vg[(size_t)(k0 + vk) * DH + vc + (i << 2)];
        __syncthreads();
        {
            __half* pd = &Ps[tid * PVS];
            *(float4*)(pd + 0)  = p0;
            *(float4*)(pd + 8)  = p1;
            *(float4*)(pd + 16) = p2;
            *(float4*)(pd + 24) = p3;
#pragma unroll
            for (int i = 0; i < 4; i++) {
                Vs[(vc + (i << 2) + 0) * PVS + vk] = __float2half_rn(v4[i].x);
                Vs[(vc + (i << 2) + 1) * PVS + vk] = __float2half_rn(v4[i].y);
                Vs[(vc + (i << 2) + 2) * PVS + vk] = __float2half_rn(v4[i].z);
                Vs[(vc + (i << 2) + 3) * PVS + vk] = __float2half_rn(v4[i].w);
            }
        }
        __syncthreads();
#pragma unroll
        for (int ks = 0; ks < 32; ks += 16) {
            uint32_t bf[8][2];
#pragma unroll
            for (int ni = 0; ni < 8; ni++) {
                const __half* vb = &Vs[((ni << 3) + gq) * PVS + ks];
                bf[ni][0] = *(const uint32_t*)(vb + (t4 << 1));
                bf[ni][1] = *(const uint32_t*)(vb + (t4 << 1) + 8);
            }
#pragma unroll
            for (int mi = 0; mi < 2; mi++) {
                const int r = wm + (mi << 4) + gq;
                const __half* pa0 = &Ps[r * PVS + ks];
                const __half* pa8 = &Ps[(r + 8) * PVS + ks];
                uint32_t af[4];
                af[0] = *(const uint32_t*)(pa0 + (t4 << 1));
                af[1] = *(const uint32_t*)(pa8 + (t4 << 1));
                af[2] = *(const uint32_t*)(pa0 + (t4 << 1) + 8);
                af[3] = *(const uint32_t*)(pa8 + (t4 << 1) + 8);
#pragma unroll
                for (int ni = 0; ni < 8; ni++)
                    mma16h(acc[mi][ni], af, bf[ni]);
            }
        }
    }

    const int b = g >> 3, h = g & 7;
    float* ocb = Oc + (size_t)b * SEQ * EMB + h * 64;
#pragma unroll
    for (int mi = 0; mi < 2; mi++) {
#pragma unroll
        for (int half = 0; half < 2; half++) {
            const int lrow = wm + (mi << 4) + gq + (half << 3);
            const float izv = 1.f / Z[g * SEQ + m0 + lrow];
            float* orow = ocb + (size_t)(m0 + lrow) * EMB;
#pragma unroll
            for (int ni = 0; ni < 8; ni++) {
                const int col = (ni << 3) + (t4 << 1);
                float2 o = make_float2(acc[mi][ni][half * 2 + 0] * izv,
                                       acc[mi][ni][half * 2 + 1] * izv);
                *(float2*)&orow[col] = o;
            }
        }
    }
}

// ---------------- launcher ----------------
extern "C" void kernel_launch(void* const* d_in, const int* in_sizes, int n_in,
                              void* d_out, int out_size) {
    const float* query = (const float*)d_in[0];
    const float* gate  = (const float*)d_in[1];
    const float* ipw   = (const float*)d_in[2];
    const float* ipb   = (const float*)d_in[3];
    const float* outw  = (const float*)d_in[4];
    const float* outb  = (const float*)d_in[5];
    const float* ln1w  = (const float*)d_in[6];
    const float* ln1b  = (const float*)d_in[7];
    const float* ln2w  = (const float*)d_in[8];
    const float* ln2b  = (const float*)d_in[9];
    const float* w1    = (const float*)d_in[10];
    const float* b1    = (const float*)d_in[11];
    const float* w2    = (const float*)d_in[12];
    const float* b2    = (const float*)d_in[13];
    float* out_x = (float*)d_out;
    float* out_w = out_x + (size_t)2 * SEQ * EMB;

    float *p_nq, *p_q, *p_k, *p_v, *p_W, *p_rsum, *p_rmax, *p_rmin, *p_Z;
    float *p_Oc, *p_x, *p_h, *p_mlp;
    __half* p_P;
    cudaGetSymbolAddress((void**)&p_nq,  g_nq);
    cudaGetSymbolAddress((void**)&p_q,   g_q);
    cudaGetSymbolAddress((void**)&p_k,   g_k);
    cudaGetSymbolAddress((void**)&p_v,   g_v);
    cudaGetSymbolAddress((void**)&p_W,   g_W);
    cudaGetSymbolAddress((void**)&p_P,   g_P);
    cudaGetSymbolAddress((void**)&p_rsum,g_rsum);
    cudaGetSymbolAddress((void**)&p_rmax,g_rmax);
    cudaGetSymbolAddress((void**)&p_rmin,g_rmin);
    cudaGetSymbolAddress((void**)&p_Z,   g_Z);
    cudaGetSymbolAddress((void**)&p_Oc,  g_Oc);
    cudaGetSymbolAddress((void**)&p_x,   g_x);
    cudaGetSymbolAddress((void**)&p_h,   g_h);
    cudaGetSymbolAddress((void**)&p_mlp, g_mlp);

    cudaFuncSetAttribute(sgemm_mma<0>, cudaFuncAttributeMaxDynamicSharedMemorySize, MM_SMEM);
    cudaFuncSetAttribute(sgemm_mma<1>, cudaFuncAttributeMaxDynamicSharedMemorySize, MM_SMEM);
    cudaFuncSetAttribute(sgemm_mma<2>, cudaFuncAttributeMaxDynamicSharedMemorySize, MM_SMEM);
    cudaFuncSetAttribute(scores_mma,   cudaFuncAttributeMaxDynamicSharedMemorySize, SC_SMEM);
    cudaFuncSetAttribute(sfmax_avg,    cudaFuncAttributeMaxDynamicSharedMemorySize, AW_SMEM);

    init_stats<<<(GH * SEQ + 255) / 256, 256>>>(p_rsum, p_rmax, p_rmin);
    ln_kernel<<<MR, 256>>>(query, ln1w, ln1b, p_nq);
    sgemm_mma<0><<<dim3(12, 32), 256, MM_SMEM>>>(p_nq, ipw, ipb, nullptr, p_q, p_k, p_v, 1536, EMB);
    scores_mma<<<dim3(16, 16, GH), 256, SC_SMEM>>>(p_q, p_k, gate, p_W, p_rsum, p_rmax, p_rmin);
    sfmax_avg<<<dim3(SEQ, 2), 256, AW_SMEM>>>(p_W, p_rsum, p_rmax, p_rmin, p_P, p_Z, out_w);
    pv_mma<<<dim3(16, GH), 128>>>(p_P, p_v, p_Z, p_Oc);
    sgemm_mma<1><<<dim3(4, 32), 256, MM_SMEM>>>(p_Oc, outw, outb, query, p_x, nullptr, nullptr, EMB, EMB);
    ln_kernel<<<MR, 256>>>(p_x, ln2w, ln2b, p_h);
    sgemm_mma<2><<<dim3(16, 32), 256, MM_SMEM>>>(p_h, w1, b1, nullptr, p_mlp, nullptr, nullptr, MLPD, EMB);
    sgemm_mma<1><<<dim3(4, 32), 256, MM_SMEM>>>(p_mlp, w2, b2, p_x, out_x, nullptr, nullptr, EMB, MLPD);
}

// round 12
// speedup vs baseline: 1.1354x; 1.1354x over previous
#include <cuda_runtime.h>
#include <cuda_fp16.h>
#include <math.h>
#include <float.h>
#include <stdint.h>

// Problem constants
#define GH   16        // B*H groups
#define SEQ  2048
#define EMB  512
#define DH   64
#define MR   4096      // B*S rows
#define MLPD 2048

typedef unsigned long long u64;

// ---------------- scratch (static device globals; no allocation) ----------------
__device__ float  g_nq [MR*EMB];
__device__ float  g_q  [MR*EMB];
__device__ float  g_k  [MR*EMB];
__device__ float  g_v  [MR*EMB];
__device__ float  g_W  [(size_t)GH*SEQ*SEQ];     // 256MB raw gated scores (fp32)
__device__ __half g_P  [(size_t)GH*SEQ*SEQ];     // 128MB exp'd (un-normalized) probs
__device__ float  g_rsum[GH*SEQ];
__device__ float  g_rmax[GH*SEQ];
__device__ float  g_rmin[GH*SEQ];
__device__ float  g_Z  [GH*SEQ];
__device__ float  g_Oc [MR*EMB];
__device__ float  g_x  [MR*EMB];
__device__ float  g_h  [MR*EMB];
__device__ float  g_mlp[(size_t)MR*MLPD];

// ---------------- misc helpers ----------------
__device__ __forceinline__ void atomicMaxF(float* addr, float val) {
    int old = __float_as_int(*addr);
    while (__int_as_float(old) < val) {
        int assumed = old;
        old = atomicCAS((int*)addr, assumed, __float_as_int(val));
        if (old == assumed) break;
    }
}
__device__ __forceinline__ void atomicMinF(float* addr, float val) {
    int old = __float_as_int(*addr);
    while (__int_as_float(old) > val) {
        int assumed = old;
        old = atomicCAS((int*)addr, assumed, __float_as_int(val));
        if (old == assumed) break;
    }
}

// ---------------- tf32 / mma helpers ----------------
__device__ __forceinline__ float tf32r(float x) {
    uint32_t r; asm("cvt.rna.tf32.f32 %0, %1;" : "=r"(r) : "f"(x));
    return __uint_as_float(r);
}
__device__ __forceinline__ void mma8(float* c, const uint32_t* a, const uint32_t* b) {
    asm volatile(
        "mma.sync.aligned.m16n8k8.row.col.f32.tf32.tf32.f32 "
        "{%0,%1,%2,%3}, {%4,%5,%6,%7}, {%8,%9}, {%0,%1,%2,%3};"
        : "+f"(c[0]), "+f"(c[1]), "+f"(c[2]), "+f"(c[3])
        : "r"(a[0]), "r"(a[1]), "r"(a[2]), "r"(a[3]), "r"(b[0]), "r"(b[1]));
}
__device__ __forceinline__ void mma16h(float* c, const uint32_t* a, const uint32_t* b) {
    asm volatile(
        "mma.sync.aligned.m16n8k16.row.col.f32.f16.f16.f32 "
        "{%0,%1,%2,%3}, {%4,%5,%6,%7}, {%8,%9}, {%0,%1,%2,%3};"
        : "+f"(c[0]), "+f"(c[1]), "+f"(c[2]), "+f"(c[3])
        : "r"(a[0]), "r"(a[1]), "r"(a[2]), "r"(a[3]), "r"(b[0]), "r"(b[1]));
}

// ======== ROUND-4/6 dense GEMM (validated): C[m,n]=sum_k A[m,k]B[n,k]+bias ========
#define MM_PAD   36
#define MM_ARR   (128 * MM_PAD)
#define MM_SMEM  (4 * MM_ARR * 4)                  // 73728 B

template <int EPI>
__global__ __launch_bounds__(256, 2)
void sgemm_mma(const float* __restrict__ A, const float* __restrict__ B,
               const float* __restrict__ bias, const float* __restrict__ res,
               float* __restrict__ C0, float* __restrict__ C1, float* __restrict__ C2,
               int N, int K) {
    extern __shared__ float sm[];
    float* sAh = sm;
    float* sAl = sm + 1 * MM_ARR;
    float* sBh = sm + 2 * MM_ARR;
    float* sBl = sm + 3 * MM_ARR;

    const int tid = threadIdx.x;
    const int wid = tid >> 5, lid = tid & 31;
    const int g = lid >> 2, t4 = lid & 3;
    const int wm = (wid >> 2) << 6;
    const int wn = (wid & 3) << 5;
    const int m0 = blockIdx.y << 7, n0 = blockIdx.x << 7;
    const int nc = K >> 5;

    const int lrow = tid >> 1;
    const int lkb  = (tid & 1) << 4;
    const float* Arow = A + (size_t)(m0 + lrow) * K + lkb;
    const float* Brow = B + (size_t)(n0 + lrow) * K + lkb;

    float4 ra[4], rb[4];
    auto load_regs = [&](int c) {
        const int kc = c << 5;
#pragma unroll
        for (int i = 0; i < 4; i++) {
            ra[i] = *(const float4*)(Arow + kc + (i << 2));
            rb[i] = *(const float4*)(Brow + kc + (i << 2));
        }
    };
    auto store_smem = [&]() {
        const int base = lrow * MM_PAD + lkb;
#pragma unroll
        for (int i = 0; i < 4; i++) {
            float4 a = ra[i], b = rb[i];
            float4 ah, al, bh, bl;
            ah.x = tf32r(a.x); al.x = tf32r(a.x - ah.x);
            ah.y = tf32r(a.y); al.y = tf32r(a.y - ah.y);
            ah.z = tf32r(a.z); al.z = tf32r(a.z - ah.z);
            ah.w = tf32r(a.w); al.w = tf32r(a.w - ah.w);
            bh.x = tf32r(b.x); bl.x = tf32r(b.x - bh.x);
            bh.y = tf32r(b.y); bl.y = tf32r(b.y - bh.y);
            bh.z = tf32r(b.z); bl.z = tf32r(b.z - bh.z);
            bh.w = tf32r(b.w); bl.w = tf32r(b.w - bh.w);
            *(float4*)&sAh[base + (i << 2)] = ah;
            *(float4*)&sAl[base + (i << 2)] = al;
            *(float4*)&sBh[base + (i << 2)] = bh;
            *(float4*)&sBl[base + (i << 2)] = bl;
        }
    };

    float acc[4][4][4];
#pragma unroll
    for (int mi = 0; mi < 4; mi++)
#pragma unroll
        for (int ni = 0; ni < 4; ni++)
#pragma unroll
            for (int f = 0; f < 4; f++) acc[mi][ni][f] = 0.f;

    load_regs(0);
    store_smem();
    __syncthreads();

    for (int c = 0; c < nc; c++) {
        if (c + 1 < nc) load_regs(c + 1);
#pragma unroll
        for (int ki = 0; ki < 4; ki++) {
            const int kc = (ki << 3) + t4;
            uint32_t bh[4][2], bl[4][2];
#pragma unroll
            for (int ni = 0; ni < 4; ni++) {
                const int nn = (wn + (ni << 3) + g) * MM_PAD;
                bh[ni][0] = __float_as_uint(sBh[nn + kc]);
                bh[ni][1] = __float_as_uint(sBh[nn + kc + 4]);
                bl[ni][0] = __float_as_uint(sBl[nn + kc]);
                bl[ni][1] = __float_as_uint(sBl[nn + kc + 4]);
            }
#pragma unroll
            for (int mi = 0; mi < 4; mi++) {
                const int r0 = (wm + (mi << 4) + g) * MM_PAD;
                const int r8 = r0 + (MM_PAD << 3);
                uint32_t ah[4], al[4];
                ah[0] = __float_as_uint(sAh[r0 + kc]);
                ah[1] = __float_as_uint(sAh[r8 + kc]);
                ah[2] = __float_as_uint(sAh[r0 + kc + 4]);
                ah[3] = __float_as_uint(sAh[r8 + kc + 4]);
                al[0] = __float_as_uint(sAl[r0 + kc]);
                al[1] = __float_as_uint(sAl[r8 + kc]);
                al[2] = __float_as_uint(sAl[r0 + kc + 4]);
                al[3] = __float_as_uint(sAl[r8 + kc + 4]);
#pragma unroll
                for (int ni = 0; ni < 4; ni++) {
                    mma8(acc[mi][ni], ah, bh[ni]);
                    mma8(acc[mi][ni], ah, bl[ni]);
                    mma8(acc[mi][ni], al, bh[ni]);
                }
            }
        }
        __syncthreads();
        if (c + 1 < nc) {
            store_smem();
            __syncthreads();
        }
    }

    auto epi2 = [&](int row, int col, float v0, float v1) {
        v0 += bias[col]; v1 += bias[col + 1];
        if (EPI == 0) {
            float* dst = (col < 512) ? C0 : ((col < 1024) ? C1 : C2);
            *(float2*)&dst[(size_t)row * 512 + (col & 511)] = make_float2(v0, v1);
        } else if (EPI == 1) {
            float2 rv = *(const float2*)&res[(size_t)row * N + col];
            *(float2*)&C0[(size_t)row * N + col] = make_float2(v0 + rv.x, v1 + rv.y);
        } else {
            float2 o;
            o.x = 0.5f * v0 * (1.f + erff(v0 * 0.7071067811865475f));
            o.y = 0.5f * v1 * (1.f + erff(v1 * 0.7071067811865475f));
            *(float2*)&C0[(size_t)row * N + col] = o;
        }
    };
#pragma unroll
    for (int mi = 0; mi < 4; mi++) {
        const int r = m0 + wm + (mi << 4) + g;
#pragma unroll
        for (int ni = 0; ni < 4; ni++) {
            const int cn = n0 + wn + (ni << 3) + (t4 << 1);
            epi2(r,     cn, acc[mi][ni][0], acc[mi][ni][1]);
            epi2(r + 8, cn, acc[mi][ni][2], acc[mi][ni][3]);
        }
    }
}

// ======== scores: 128x64 tile, 3 CTAs/SM, round-6 epilogue pattern ========
// W = (Q K^T)*gate + per-row sum/max/min stats.
#define PR        36
#define A_PAIRS   (128 * PR)
#define B_PAIRS   (64 * PR)
#define SC_SMEM   ((A_PAIRS + B_PAIRS) * 8)   // 55296 bytes

__device__ __forceinline__ void split_store16(float2* dst, int basep, const float4* r) {
#pragma unroll
    for (int i = 0; i < 4; i++) {
        float4 v = r[i];
        float h0 = tf32r(v.x), h1 = tf32r(v.y), h2 = tf32r(v.z), h3 = tf32r(v.w);
        float l0 = tf32r(v.x - h0), l1 = tf32r(v.y - h1);
        float l2 = tf32r(v.z - h2), l3 = tf32r(v.w - h3);
        *(float4*)(dst + basep + (i << 2))     = make_float4(h0, l0, h1, l1);
        *(float4*)(dst + basep + (i << 2) + 2) = make_float4(h2, l2, h3, l3);
    }
}
__device__ __forceinline__ void split_store8(float2* dst, int basep, float4 r0, float4 r1) {
    float4 rr[2] = { r0, r1 };
#pragma unroll
    for (int i = 0; i < 2; i++) {
        float4 v = rr[i];
        float h0 = tf32r(v.x), h1 = tf32r(v.y), h2 = tf32r(v.z), h3 = tf32r(v.w);
        float l0 = tf32r(v.x - h0), l1 = tf32r(v.y - h1);
        float l2 = tf32r(v.z - h2), l3 = tf32r(v.w - h3);
        *(float4*)(dst + basep + (i << 2))     = make_float4(h0, l0, h1, l1);
        *(float4*)(dst + basep + (i << 2) + 2) = make_float4(h2, l2, h3, l3);
    }
}

__global__ __launch_bounds__(256, 3)
void scores_mma(const float* __restrict__ Q, const float* __restrict__ Km,
                const float* __restrict__ gate, float* __restrict__ W,
                float* __restrict__ rsum, float* __restrict__ rmaxp,
                float* __restrict__ rminp) {
    extern __shared__ float2 s2[];
    float2* sA2 = s2;
    float2* sB2 = s2 + A_PAIRS;

    const int g = blockIdx.z;
    const int tid = threadIdx.x;
    const int wid = tid >> 5, lid = tid & 31;
    const int gq = lid >> 2, t4 = lid & 3;
    const int wm = (wid >> 1) << 5;     // 0,32,64,96 (4 m-warps)
    const int wn = (wid & 1) << 5;      // 0,32       (2 n-warps)
    const int i0 = blockIdx.y << 7, j0 = blockIdx.x << 6;

    // A loads: 2 threads/row, 16 floats each (128 rows)
    const int lrowA = tid >> 1;
    const int lkbA  = (tid & 1) << 4;
    const int basepA = lrowA * PR + lkbA;
    const float* Arow = Q + (size_t)g * SEQ * DH + (size_t)(i0 + lrowA) * DH + lkbA;
    // B loads: 4 threads/row, 8 floats each (64 rows)
    const int lrowB = tid >> 2;
    const int lkbB  = (tid & 3) << 3;
    const int basepB = lrowB * PR + lkbB;
    const float* Brow = Km + (size_t)g * SEQ * DH + (size_t)(j0 + lrowB) * DH + lkbB;

    float acc[2][4][4];
#pragma unroll
    for (int mi = 0; mi < 2; mi++)
#pragma unroll
        for (int ni = 0; ni < 4; ni++)
#pragma unroll
            for (int f = 0; f < 4; f++) acc[mi][ni][f] = 0.f;

#pragma unroll
    for (int c = 0; c < 2; c++) {
        const int kc = c << 5;
        float4 ra[4];
#pragma unroll
        for (int i = 0; i < 4; i++)
            ra[i] = *(const float4*)(Arow + kc + (i << 2));
        float4 rb0 = *(const float4*)(Brow + kc);
        float4 rb1 = *(const float4*)(Brow + kc + 4);
        if (c) __syncthreads();
        split_store16(sA2, basepA, ra);
        split_store8(sB2, basepB, rb0, rb1);
        __syncthreads();
        // mma over this chunk
#pragma unroll
        for (int ki = 0; ki < 4; ki++) {
            const int kcc = (ki << 3) + t4;
            uint32_t bh[4][2], bl[4][2];
#pragma unroll
            for (int ni = 0; ni < 4; ni++) {
                const int nn = (wn + (ni << 3) + gq) * PR;
                float2 b0 = sB2[nn + kcc];
                float2 b1 = sB2[nn + kcc + 4];
                bh[ni][0] = __float_as_uint(b0.x); bh[ni][1] = __float_as_uint(b1.x);
                bl[ni][0] = __float_as_uint(b0.y); bl[ni][1] = __float_as_uint(b1.y);
            }
#pragma unroll
            for (int mi = 0; mi < 2; mi++) {
                const int r0 = (wm + (mi << 4) + gq) * PR, r8 = r0 + (PR << 3);
                float2 a00 = sA2[r0 + kcc], a01 = sA2[r0 + kcc + 4];
                float2 a10 = sA2[r8 + kcc], a11 = sA2[r8 + kcc + 4];
                uint32_t ah[4] = { __float_as_uint(a00.x), __float_as_uint(a10.x),
                                   __float_as_uint(a01.x), __float_as_uint(a11.x) };
                uint32_t al[4] = { __float_as_uint(a00.y), __float_as_uint(a10.y),
                                   __float_as_uint(a01.y), __float_as_uint(a11.y) };
#pragma unroll
                for (int ni = 0; ni < 4; ni++) {
                    mma8(acc[mi][ni], ah, bh[ni]);
                    mma8(acc[mi][ni], ah, bl[ni]);
                    mma8(acc[mi][ni], al, bh[ni]);
                }
            }
        }
    }

    // ---- epilogue (round-6 pattern): gate mult, W store, stats ----
    __syncthreads();
    float* sred = (float*)s2;           // [3][2][128] = 3KB
    const size_t wb = (size_t)g * SEQ * SEQ;

#pragma unroll
    for (int mi = 0; mi < 2; mi++) {
#pragma unroll
        for (int half = 0; half < 2; half++) {
            const int row = wm + (mi << 4) + gq + (half << 3);
            const int grow = i0 + row;
            float s = 0.f, mx = -FLT_MAX, mn = FLT_MAX;
#pragma unroll
            for (int ni = 0; ni < 4; ni++) {
                const int cn = j0 + wn + (ni << 3) + (t4 << 1);
                const size_t off = wb + (size_t)grow * SEQ + cn;
                float2 gt = *(const float2*)&gate[off];
                float v0 = acc[mi][ni][half * 2 + 0] * gt.x;
                float v1 = acc[mi][ni][half * 2 + 1] * gt.y;
                *(float2*)&W[off] = make_float2(v0, v1);
                s += v0 + v1;
                mx = fmaxf(mx, fmaxf(v0, v1));
                mn = fminf(mn, fminf(v0, v1));
            }
#pragma unroll
            for (int o = 1; o < 4; o <<= 1) {
                s += __shfl_xor_sync(~0u, s, o);
                mx = fmaxf(mx, __shfl_xor_sync(~0u, mx, o));
                mn = fminf(mn, __shfl_xor_sync(~0u, mn, o));
            }
            if (t4 == 0) {
                const int wi = wid & 1;
                sred[0 * 256 + wi * 128 + row] = s;
                sred[1 * 256 + wi * 128 + row] = mx;
                sred[2 * 256 + wi * 128 + row] = mn;
            }
        }
    }
    __syncthreads();
    if (tid < 128) {
        float s  = sred[tid] + sred[128 + tid];
        float mx = fmaxf(sred[256 + tid], sred[256 + 128 + tid]);
        float mn = fminf(sred[512 + tid], sred[512 + 128 + tid]);
        const int r = g * SEQ + i0 + tid;
        atomicAdd(&rsum[r], s);
        atomicMaxF(&rmaxp[r], mx);
        atomicMinF(&rminp[r], mn);
    }
}

__global__ void init_stats(float* rsum, float* rmax, float* rmin) {
    int i = blockIdx.x * blockDim.x + threadIdx.x;
    if (i < GH * SEQ) { rsum[i] = 0.f; rmax[i] = -FLT_MAX; rmin[i] = FLT_MAX; }
}

// ---------------- LayerNorm (1 block / row of 512) ----------------
__global__ void ln_kernel(const float* __restrict__ x, const float* __restrict__ w,
                          const float* __restrict__ b, float* __restrict__ y) {
    int row = blockIdx.x;
    const float* xr = x + (size_t)row * EMB;
    int t = threadIdx.x;
    float v0 = xr[t], v1 = xr[t + 256];
    float s = v0 + v1, q = v0 * v0 + v1 * v1;
#pragma unroll
    for (int off = 16; off; off >>= 1) {
        s += __shfl_xor_sync(~0u, s, off);
        q += __shfl_xor_sync(~0u, q, off);
    }
    __shared__ float ss[8], sq[8];
    if ((t & 31) == 0) { ss[t >> 5] = s; sq[t >> 5] = q; }
    __syncthreads();
    if (t == 0) {
        float s2 = 0.f, q2 = 0.f;
#pragma unroll
        for (int i = 0; i < 8; i++) { s2 += ss[i]; q2 += sq[i]; }
        ss[0] = s2; sq[0] = q2;
    }
    __syncthreads();
    float mean = ss[0] * (1.f / EMB);
    float var  = sq[0] * (1.f / EMB) - mean * mean;
    float rstd = rsqrtf(var + 1e-5f);
    float* yr = y + (size_t)row * EMB;
    yr[t]       = (v0 - mean) * rstd * w[t]       + b[t];
    yr[t + 256] = (v1 - mean) * rstd * w[t + 256] + b[t + 256];
}

// ======== fused: exp -> P fp16, Z, head-averaged attn weights (round-10) ========
#define AW_SMEM (8 * SEQ * 2)   // 32768 bytes of half
__global__ void sfmax_avg(const float* __restrict__ W, const float* __restrict__ rsum,
                          const float* __restrict__ rmaxp, const float* __restrict__ rminp,
                          __half* __restrict__ P, float* __restrict__ Z,
                          float* __restrict__ out) {
    extern __shared__ __half sph[];     // [8][2048] half
    __shared__ float sz[8];
    const int i = blockIdx.x, b = blockIdx.y;
    const int tid = threadIdx.x;
    if (tid < 8) sz[tid] = 0.f;
    __syncthreads();

    float inv[8], mh[8], z[8];
    int rowh[8];
#pragma unroll
    for (int h = 0; h < 8; h++) {
        rowh[h] = (b * 8 + h) * SEQ + i;
        float s = rsum[rowh[h]] + 1e-12f;
        inv[h] = 1.f / s;
        mh[h] = (s > 0.f) ? rmaxp[rowh[h]] * inv[h] : rminp[rowh[h]] * inv[h];
        z[h] = 0.f;
    }

#pragma unroll
    for (int k = 0; k < 2; k++) {
        const int j = (tid + (k << 8)) << 2;
        float4 w4[8];
#pragma unroll
        for (int h = 0; h < 8; h++)
            w4[h] = *(const float4*)&W[(size_t)rowh[h] * SEQ + j];
#pragma unroll
        for (int h = 0; h < 8; h++) {
            float4 p;
            p.x = __expf(fmaf(w4[h].x, inv[h], -mh[h]));
            p.y = __expf(fmaf(w4[h].y, inv[h], -mh[h]));
            p.z = __expf(fmaf(w4[h].z, inv[h], -mh[h]));
            p.w = __expf(fmaf(w4[h].w, inv[h], -mh[h]));
            __half2 h0 = __floats2half2_rn(p.x, p.y);
            __half2 h1 = __floats2half2_rn(p.z, p.w);
            uint2 pk = make_uint2(*(uint32_t*)&h0, *(uint32_t*)&h1);
            *(uint2*)&P[(size_t)rowh[h] * SEQ + j] = pk;
            *(uint2*)&sph[h * SEQ + j] = pk;
            z[h] += (p.x + p.y) + (p.z + p.w);
        }
    }
#pragma unroll
    for (int h = 0; h < 8; h++) {
#pragma unroll
        for (int off = 16; off; off >>= 1) z[h] += __shfl_xor_sync(~0u, z[h], off);
    }
    if ((tid & 31) == 0) {
#pragma unroll
        for (int h = 0; h < 8; h++) atomicAdd(&sz[h], z[h]);
    }
    __syncthreads();
    if (tid < 8) Z[(b * 8 + tid) * SEQ + i] = sz[tid];
    float iz[8];
#pragma unroll
    for (int h = 0; h < 8; h++) iz[h] = 0.125f / sz[h];
    float* orow = out + (size_t)b * SEQ * SEQ + (size_t)i * SEQ;
#pragma unroll
    for (int k = 0; k < 2; k++) {
        const int j = (tid + (k << 8)) << 2;
        float4 a = make_float4(0.f, 0.f, 0.f, 0.f);
#pragma unroll
        for (int h = 0; h < 8; h++) {
            uint2 pk = *(const uint2*)&sph[h * SEQ + j];
            float2 p01 = __half22float2(*(__half2*)&pk.x);
            float2 p23 = __half22float2(*(__half2*)&pk.y);
            a.x = fmaf(p01.x, iz[h], a.x);
            a.y = fmaf(p01.y, iz[h], a.y);
            a.z = fmaf(p23.x, iz[h], a.z);
            a.w = fmaf(p23.y, iz[h], a.w);
        }
        *(float4*)&orow[j] = a;
    }
}

// ======== PV via fp16 mma: Oc[(b,s),h*64+d] = (sum_k P[g,s,k] V[g,k,d]) / Z ========
#define PVS 40
__global__ __launch_bounds__(128, 4)
void pv_mma(const __half* __restrict__ P, const float* __restrict__ V,
            const float* __restrict__ Z, float* __restrict__ Oc) {
    __shared__ __half Ps[128 * PVS];
    __shared__ __half Vs[64 * PVS];
    const int g = blockIdx.y;
    const int m0 = blockIdx.x << 7;
    const int tid = threadIdx.x;
    const int wid = tid >> 5, lid = tid & 31;
    const int gq = lid >> 2, t4 = lid & 3;
    const int wm = wid << 5;

    const __half* Pg = P + (size_t)g * SEQ * SEQ;
    const float*  Vg = V + (size_t)g * SEQ * DH;

    float acc[2][8][4];
#pragma unroll
    for (int mi = 0; mi < 2; mi++)
#pragma unroll
        for (int ni = 0; ni < 8; ni++)
#pragma unroll
            for (int f = 0; f < 4; f++) acc[mi][ni][f] = 0.f;

    const int vk = tid >> 2;
    const int vc = (tid & 3) << 4;

    for (int k0 = 0; k0 < SEQ; k0 += 32) {
        const __half* prow = Pg + (size_t)(m0 + tid) * SEQ + k0;
        float4 p0 = *(const float4*)(prow + 0);
        float4 p1 = *(const float4*)(prow + 8);
        float4 p2 = *(const float4*)(prow + 16);
        float4 p3 = *(const float4*)(prow + 24);
        float4 v4[4];
#pragma unroll
        for (int i = 0; i < 4; i++)
            v4[i] = *(const float4*)&Vg[(size_t)(k0 + vk) * DH + vc + (i << 2)];
        __syncthreads();
        {
            __half* pd = &Ps[tid * PVS];
            *(float4*)(pd + 0)  = p0;
            *(float4*)(pd + 8)  = p1;
            *(float4*)(pd + 16) = p2;
            *(float4*)(pd + 24) = p3;
#pragma unroll
            for (int i = 0; i < 4; i++) {
                Vs[(vc + (i << 2) + 0) * PVS + vk] = __float2half_rn(v4[i].x);
                Vs[(vc + (i << 2) + 1) * PVS + vk] = __float2half_rn(v4[i].y);
                Vs[(vc + (i << 2) + 2) * PVS + vk] = __float2half_rn(v4[i].z);
                Vs[(vc + (i << 2) + 3) * PVS + vk] = __float2half_rn(v4[i].w);
            }
        }
        __syncthreads();
#pragma unroll
        for (int ks = 0; ks < 32; ks += 16) {
            uint32_t bf[8][2];
#pragma unroll
            for (int ni = 0; ni < 8; ni++) {
                const __half* vb = &Vs[((ni << 3) + gq) * PVS + ks];
                bf[ni][0] = *(const uint32_t*)(vb + (t4 << 1));
                bf[ni][1] = *(const uint32_t*)(vb + (t4 << 1) + 8);
            }
#pragma unroll
            for (int mi = 0; mi < 2; mi++) {
                const int r = wm + (mi << 4) + gq;
                const __half* pa0 = &Ps[r * PVS + ks];
                const __half* pa8 = &Ps[(r + 8) * PVS + ks];
                uint32_t af[4];
                af[0] = *(const uint32_t*)(pa0 + (t4 << 1));
                af[1] = *(const uint32_t*)(pa8 + (t4 << 1));
                af[2] = *(const uint32_t*)(pa0 + (t4 << 1) + 8);
                af[3] = *(const uint32_t*)(pa8 + (t4 << 1) + 8);
#pragma unroll
                for (int ni = 0; ni < 8; ni++)
                    mma16h(acc[mi][ni], af, bf[ni]);
            }
        }
    }

    const int b = g >> 3, h = g & 7;
    float* ocb = Oc + (size_t)b * SEQ * EMB + h * 64;
#pragma unroll
    for (int mi = 0; mi < 2; mi++) {
#pragma unroll
        for (int half = 0; half < 2; half++) {
            const int lrow = wm + (mi << 4) + gq + (half << 3);
            const float izv = 1.f / Z[g * SEQ + m0 + lrow];
            float* orow = ocb + (size_t)(m0 + lrow) * EMB;
#pragma unroll
            for (int ni = 0; ni < 8; ni++) {
                const int col = (ni << 3) + (t4 << 1);
                float2 o = make_float2(acc[mi][ni][half * 2 + 0] * izv,
                                       acc[mi][ni][half * 2 + 1] * izv);
                *(float2*)&orow[col] = o;
            }
        }
    }
}

// ---------------- launcher ----------------
extern "C" void kernel_launch(void* const* d_in, const int* in_sizes, int n_in,
                              void* d_out, int out_size) {
    const float* query = (const float*)d_in[0];
    const float* gate  = (const float*)d_in[1];
    const float* ipw   = (const float*)d_in[2];
    const float* ipb   = (const float*)d_in[3];
    const float* outw  = (const float*)d_in[4];
    const float* outb  = (const float*)d_in[5];
    const float* ln1w  = (const float*)d_in[6];
    const float* ln1b  = (const float*)d_in[7];
    const float* ln2w  = (const float*)d_in[8];
    const float* ln2b  = (const float*)d_in[9];
    const float* w1    = (const float*)d_in[10];
    const float* b1    = (const float*)d_in[11];
    const float* w2    = (const float*)d_in[12];
    const float* b2    = (const float*)d_in[13];
    float* out_x = (float*)d_out;
    float* out_w = out_x + (size_t)2 * SEQ * EMB;

    float *p_nq, *p_q, *p_k, *p_v, *p_W, *p_rsum, *p_rmax, *p_rmin, *p_Z;
    float *p_Oc, *p_x, *p_h, *p_mlp;
    __half* p_P;
    cudaGetSymbolAddress((void**)&p_nq,  g_nq);
    cudaGetSymbolAddress((void**)&p_q,   g_q);
    cudaGetSymbolAddress((void**)&p_k,   g_k);
    cudaGetSymbolAddress((void**)&p_v,   g_v);
    cudaGetSymbolAddress((void**)&p_W,   g_W);
    cudaGetSymbolAddress((void**)&p_P,   g_P);
    cudaGetSymbolAddress((void**)&p_rsum,g_rsum);
    cudaGetSymbolAddress((void**)&p_rmax,g_rmax);
    cudaGetSymbolAddress((void**)&p_rmin,g_rmin);
    cudaGetSymbolAddress((void**)&p_Z,   g_Z);
    cudaGetSymbolAddress((void**)&p_Oc,  g_Oc);
    cudaGetSymbolAddress((void**)&p_x,   g_x);
    cudaGetSymbolAddress((void**)&p_h,   g_h);
    cudaGetSymbolAddress((void**)&p_mlp, g_mlp);

    cudaFuncSetAttribute(sgemm_mma<0>, cudaFuncAttributeMaxDynamicSharedMemorySize, MM_SMEM);
    cudaFuncSetAttribute(sgemm_mma<1>, cudaFuncAttributeMaxDynamicSharedMemorySize, MM_SMEM);
    cudaFuncSetAttribute(sgemm_mma<2>, cudaFuncAttributeMaxDynamicSharedMemorySize, MM_SMEM);
    cudaFuncSetAttribute(scores_mma,   cudaFuncAttributeMaxDynamicSharedMemorySize, SC_SMEM);
    cudaFuncSetAttribute(sfmax_avg,    cudaFuncAttributeMaxDynamicSharedMemorySize, AW_SMEM);

    init_stats<<<(GH * SEQ + 255) / 256, 256>>>(p_rsum, p_rmax, p_rmin);
    ln_kernel<<<MR, 256>>>(query, ln1w, ln1b, p_nq);
    sgemm_mma<0><<<dim3(12, 32), 256, MM_SMEM>>>(p_nq, ipw, ipb, nullptr, p_q, p_k, p_v, 1536, EMB);
    scores_mma<<<dim3(32, 16, GH), 256, SC_SMEM>>>(p_q, p_k, gate, p_W, p_rsum, p_rmax, p_rmin);
    sfmax_avg<<<dim3(SEQ, 2), 256, AW_SMEM>>>(p_W, p_rsum, p_rmax, p_rmin, p_P, p_Z, out_w);
    pv_mma<<<dim3(16, GH), 128>>>(p_P, p_v, p_Z, p_Oc);
    sgemm_mma<1><<<dim3(4, 32), 256, MM_SMEM>>>(p_Oc, outw, outb, query, p_x, nullptr, nullptr, EMB, EMB);
    ln_kernel<<<MR, 256>>>(p_x, ln2w, ln2b, p_h);
    sgemm_mma<2><<<dim3(16, 32), 256, MM_SMEM>>>(p_h, w1, b1, nullptr, p_mlp, nullptr, nullptr, MLPD, EMB);
    sgemm_mma<1><<<dim3(4, 32), 256, MM_SMEM>>>(p_mlp, w2, b2, p_x, out_x, nullptr, nullptr, EMB, MLPD);
}

// round 13
// speedup vs baseline: 1.5230x; 1.3414x over previous
#include <cuda_runtime.h>
#include <cuda_fp16.h>
#include <cuda_bf16.h>
#include <math.h>
#include <float.h>
#include <stdint.h>

// Problem constants
#define GH   16        // B*H groups
#define SEQ  2048
#define EMB  512
#define DH   64
#define MR   4096      // B*S rows
#define MLPD 2048

typedef unsigned long long u64;

// ---------------- scratch (static device globals; no allocation) ----------------
__device__ float  g_nq [MR*EMB];
__device__ float  g_q  [MR*EMB];
__device__ float  g_k  [MR*EMB];
__device__ float  g_v  [MR*EMB];
__device__ float  g_W  [(size_t)GH*SEQ*SEQ];     // 256MB raw gated scores (fp32)
__device__ __half g_P  [(size_t)GH*SEQ*SEQ];     // 128MB exp'd (un-normalized) probs
__device__ float  g_rsum[GH*SEQ];
__device__ float  g_rmax[GH*SEQ];
__device__ float  g_rmin[GH*SEQ];
__device__ float  g_Z  [GH*SEQ];
__device__ float  g_Oc [MR*EMB];
__device__ float  g_x  [MR*EMB];
__device__ float  g_h  [MR*EMB];
__device__ float  g_mlp[(size_t)MR*MLPD];

// ---------------- misc helpers ----------------
__device__ __forceinline__ void atomicMaxF(float* addr, float val) {
    int old = __float_as_int(*addr);
    while (__int_as_float(old) < val) {
        int assumed = old;
        old = atomicCAS((int*)addr, assumed, __float_as_int(val));
        if (old == assumed) break;
    }
}
__device__ __forceinline__ void atomicMinF(float* addr, float val) {
    int old = __float_as_int(*addr);
    while (__int_as_float(old) > val) {
        int assumed = old;
        old = atomicCAS((int*)addr, assumed, __float_as_int(val));
        if (old == assumed) break;
    }
}

// ---------------- mma helpers ----------------
__device__ __forceinline__ void mmabf(float* c, const uint32_t* a, const uint32_t* b) {
    asm volatile(
        "mma.sync.aligned.m16n8k16.row.col.f32.bf16.bf16.f32 "
        "{%0,%1,%2,%3}, {%4,%5,%6,%7}, {%8,%9}, {%0,%1,%2,%3};"
        : "+f"(c[0]), "+f"(c[1]), "+f"(c[2]), "+f"(c[3])
        : "r"(a[0]), "r"(a[1]), "r"(a[2]), "r"(a[3]), "r"(b[0]), "r"(b[1]));
}
__device__ __forceinline__ void mma16h(float* c, const uint32_t* a, const uint32_t* b) {
    asm volatile(
        "mma.sync.aligned.m16n8k16.row.col.f32.f16.f16.f32 "
        "{%0,%1,%2,%3}, {%4,%5,%6,%7}, {%8,%9}, {%0,%1,%2,%3};"
        : "+f"(c[0]), "+f"(c[1]), "+f"(c[2]), "+f"(c[3])
        : "r"(a[0]), "r"(a[1]), "r"(a[2]), "r"(a[3]), "r"(b[0]), "r"(b[1]));
}

// split two consecutive fp32 values into packed bf16 (hi,hi) and (lo,lo) pairs
__device__ __forceinline__ void bfsplit2(float x, float y, uint32_t& h, uint32_t& l) {
    __nv_bfloat16 hx = __float2bfloat16_rn(x);
    __nv_bfloat16 hy = __float2bfloat16_rn(y);
    float lx = x - __bfloat162float(hx);
    float ly = y - __bfloat162float(hy);
    __nv_bfloat162 hp = __halves2bfloat162(hx, hy);
    __nv_bfloat162 lp = __halves2bfloat162(__float2bfloat16_rn(lx), __float2bfloat16_rn(ly));
    h = *(uint32_t*)&hp;
    l = *(uint32_t*)&lp;
}

// ---------------- bf16-pair smem layout ----------------
// per matrix: 128 rows x 20 uint32 (32 bf16 k-values + pad); row stride 80B.
// fragment loads (20g + t4) mod 32 form a 32-bank bijection -> conflict-free.
#define RSTR   20                       // uint32 per row
#define MATU   (128 * RSTR)             // 2560 uint32 per matrix
#define MM_SMEM (4 * MATU * 4)          // Ah, Al, Bh, Bl = 40960 bytes

// one K=32 chunk = 2 k16 steps of 3xBF16 mma (shared by dense + scores)
__device__ __forceinline__ void mma_chunk_bf(const uint32_t* sAh, const uint32_t* sAl,
                                             const uint32_t* sBh, const uint32_t* sBl,
                                             int wm, int wn, int g, int t4,
                                             float (&acc)[4][4][4]) {
#pragma unroll
    for (int ks = 0; ks < 2; ks++) {
        const int kq = (ks << 3) + t4;
        uint32_t bh[4][2], bl[4][2];
#pragma unroll
        for (int ni = 0; ni < 4; ni++) {
            const int nn = (wn + (ni << 3) + g) * RSTR + kq;
            bh[ni][0] = sBh[nn]; bh[ni][1] = sBh[nn + 4];
            bl[ni][0] = sBl[nn]; bl[ni][1] = sBl[nn + 4];
        }
#pragma unroll
        for (int mi = 0; mi < 4; mi++) {
            const int r0 = (wm + (mi << 4) + g) * RSTR + kq;
            const int r8 = r0 + (RSTR << 3);
            uint32_t ah[4] = { sAh[r0], sAh[r8], sAh[r0 + 4], sAh[r8 + 4] };
            uint32_t al[4] = { sAl[r0], sAl[r8], sAl[r0 + 4], sAl[r8 + 4] };
#pragma unroll
            for (int ni = 0; ni < 4; ni++) {
                mmabf(acc[mi][ni], ah, bh[ni]);
                mmabf(acc[mi][ni], ah, bl[ni]);
                mmabf(acc[mi][ni], al, bh[ni]);
            }
        }
    }
}

// convert 16 raw floats (4 float4) to hi/lo packed pairs and store (2 x uint4 each)
__device__ __forceinline__ void split_store_bf(uint32_t* dstH, uint32_t* dstL,
                                               int base32, const float4* r) {
    uint32_t h[8], l[8];
#pragma unroll
    for (int i = 0; i < 4; i++) {
        bfsplit2(r[i].x, r[i].y, h[i * 2 + 0], l[i * 2 + 0]);
        bfsplit2(r[i].z, r[i].w, h[i * 2 + 1], l[i * 2 + 1]);
    }
    *(uint4*)&dstH[base32]     = make_uint4(h[0], h[1], h[2], h[3]);
    *(uint4*)&dstH[base32 + 4] = make_uint4(h[4], h[5], h[6], h[7]);
    *(uint4*)&dstL[base32]     = make_uint4(l[0], l[1], l[2], l[3]);
    *(uint4*)&dstL[base32 + 4] = make_uint4(l[4], l[5], l[6], l[7]);
}

// ======== dense GEMM (3xBF16): C[m,n]=sum_k A[m,k]B[n,k]+bias ========
// Block 128x128, 8 warps (2m x 4n), warp tile 64x32. K chunks of 32.
// EPI 0: qkv split; 1: +residual; 2: exact gelu.
template <int EPI>
__global__ __launch_bounds__(256, 2)
void sgemm_mma(const float* __restrict__ A, const float* __restrict__ B,
               const float* __restrict__ bias, const float* __restrict__ res,
               float* __restrict__ C0, float* __restrict__ C1, float* __restrict__ C2,
               int N, int K) {
    extern __shared__ uint32_t su[];
    uint32_t* sAh = su;
    uint32_t* sAl = su + 1 * MATU;
    uint32_t* sBh = su + 2 * MATU;
    uint32_t* sBl = su + 3 * MATU;

    const int tid = threadIdx.x;
    const int wid = tid >> 5, lid = tid & 31;
    const int g = lid >> 2, t4 = lid & 3;
    const int wm = (wid >> 2) << 6;
    const int wn = (wid & 3) << 5;
    const int m0 = blockIdx.y << 7, n0 = blockIdx.x << 7;
    const int nc = K >> 5;

    const int lrow = tid >> 1;
    const int lkb  = (tid & 1) << 4;
    const int base32 = lrow * RSTR + ((tid & 1) << 3);
    const float* Arow = A + (size_t)(m0 + lrow) * K + lkb;
    const float* Brow = B + (size_t)(n0 + lrow) * K + lkb;

    float4 ra[4], rb[4];
    auto load_regs = [&](int c) {
        const int kc = c << 5;
#pragma unroll
        for (int i = 0; i < 4; i++) {
            ra[i] = *(const float4*)(Arow + kc + (i << 2));
            rb[i] = *(const float4*)(Brow + kc + (i << 2));
        }
    };

    float acc[4][4][4];
#pragma unroll
    for (int mi = 0; mi < 4; mi++)
#pragma unroll
        for (int ni = 0; ni < 4; ni++)
#pragma unroll
            for (int f = 0; f < 4; f++) acc[mi][ni][f] = 0.f;

    load_regs(0);
    split_store_bf(sAh, sAl, base32, ra);
    split_store_bf(sBh, sBl, base32, rb);
    __syncthreads();

    for (int c = 0; c < nc; c++) {
        if (c + 1 < nc) load_regs(c + 1);
        mma_chunk_bf(sAh, sAl, sBh, sBl, wm, wn, g, t4, acc);
        __syncthreads();
        if (c + 1 < nc) {
            split_store_bf(sAh, sAl, base32, ra);
            split_store_bf(sBh, sBl, base32, rb);
            __syncthreads();
        }
    }

    auto epi2 = [&](int row, int col, float v0, float v1) {
        v0 += bias[col]; v1 += bias[col + 1];
        if (EPI == 0) {
            float* dst = (col < 512) ? C0 : ((col < 1024) ? C1 : C2);
            *(float2*)&dst[(size_t)row * 512 + (col & 511)] = make_float2(v0, v1);
        } else if (EPI == 1) {
            float2 rv = *(const float2*)&res[(size_t)row * N + col];
            *(float2*)&C0[(size_t)row * N + col] = make_float2(v0 + rv.x, v1 + rv.y);
        } else {
            float2 o;
            o.x = 0.5f * v0 * (1.f + erff(v0 * 0.7071067811865475f));
            o.y = 0.5f * v1 * (1.f + erff(v1 * 0.7071067811865475f));
            *(float2*)&C0[(size_t)row * N + col] = o;
        }
    };
#pragma unroll
    for (int mi = 0; mi < 4; mi++) {
        const int r = m0 + wm + (mi << 4) + g;
#pragma unroll
        for (int ni = 0; ni < 4; ni++) {
            const int cn = n0 + wn + (ni << 3) + (t4 << 1);
            epi2(r,     cn, acc[mi][ni][0], acc[mi][ni][1]);
            epi2(r + 8, cn, acc[mi][ni][2], acc[mi][ni][3]);
        }
    }
}

// ======== scores (3xBF16 mainloop, round-6/10 epilogue): W = (Q K^T)*gate + stats ====
#define SC_SMEM MM_SMEM

__global__ __launch_bounds__(256, 2)
void scores_mma(const float* __restrict__ Q, const float* __restrict__ Km,
                const float* __restrict__ gate, float* __restrict__ W,
                float* __restrict__ rsum, float* __restrict__ rmaxp,
                float* __restrict__ rminp) {
    extern __shared__ uint32_t su[];
    uint32_t* sAh = su;
    uint32_t* sAl = su + 1 * MATU;
    uint32_t* sBh = su + 2 * MATU;
    uint32_t* sBl = su + 3 * MATU;

    const int g = blockIdx.z;
    const int tid = threadIdx.x;
    const int wid = tid >> 5, lid = tid & 31;
    const int gq = lid >> 2, t4 = lid & 3;
    const int wm = (wid >> 2) << 6;
    const int wn = (wid & 3) << 5;
    const int i0 = blockIdx.y << 7, j0 = blockIdx.x << 7;

    const int lrow = tid >> 1;
    const int lkb  = (tid & 1) << 4;
    const int base32 = lrow * RSTR + ((tid & 1) << 3);
    const float* Arow = Q + (size_t)g * SEQ * DH + (size_t)(i0 + lrow) * DH + lkb;
    const float* Brow = Km + (size_t)g * SEQ * DH + (size_t)(j0 + lrow) * DH + lkb;

    float acc[4][4][4];
#pragma unroll
    for (int mi = 0; mi < 4; mi++)
#pragma unroll
        for (int ni = 0; ni < 4; ni++)
#pragma unroll
            for (int f = 0; f < 4; f++) acc[mi][ni][f] = 0.f;

#pragma unroll
    for (int c = 0; c < 2; c++) {
        float4 ra[4], rb[4];
        const int kc = c << 5;
#pragma unroll
        for (int i = 0; i < 4; i++) {
            ra[i] = *(const float4*)(Arow + kc + (i << 2));
            rb[i] = *(const float4*)(Brow + kc + (i << 2));
        }
        if (c) __syncthreads();
        split_store_bf(sAh, sAl, base32, ra);
        split_store_bf(sBh, sBl, base32, rb);
        __syncthreads();
        mma_chunk_bf(sAh, sAl, sBh, sBl, wm, wn, gq, t4, acc);
    }

    // ---- epilogue (round-6/10 structure): gate mult, W store, stats ----
    __syncthreads();
    float* sred = (float*)su;           // [3][4][128]
    const size_t wb = (size_t)g * SEQ * SEQ;

#pragma unroll
    for (int mi = 0; mi < 4; mi++) {
#pragma unroll
        for (int half = 0; half < 2; half++) {
            const int row = wm + (mi << 4) + gq + (half << 3);
            const int grow = i0 + row;
            float s = 0.f, mx = -FLT_MAX, mn = FLT_MAX;
#pragma unroll
            for (int ni = 0; ni < 4; ni++) {
                const int cn = j0 + wn + (ni << 3) + (t4 << 1);
                const size_t off = wb + (size_t)grow * SEQ + cn;
                float2 gt = *(const float2*)&gate[off];
                float v0 = acc[mi][ni][half * 2 + 0] * gt.x;
                float v1 = acc[mi][ni][half * 2 + 1] * gt.y;
                *(float2*)&W[off] = make_float2(v0, v1);
                s += v0 + v1;
                mx = fmaxf(mx, fmaxf(v0, v1));
                mn = fminf(mn, fminf(v0, v1));
            }
#pragma unroll
            for (int o = 1; o < 4; o <<= 1) {
                s += __shfl_xor_sync(~0u, s, o);
                mx = fmaxf(mx, __shfl_xor_sync(~0u, mx, o));
                mn = fminf(mn, __shfl_xor_sync(~0u, mn, o));
            }
            if (t4 == 0) {
                const int wi = wid & 3;
                sred[0 * 512 + wi * 128 + row] = s;
                sred[1 * 512 + wi * 128 + row] = mx;
                sred[2 * 512 + wi * 128 + row] = mn;
            }
        }
    }
    __syncthreads();
    if (tid < 128) {
        float s  = sred[tid] + sred[128 + tid] + sred[256 + tid] + sred[384 + tid];
        float mx = fmaxf(fmaxf(sred[512 + tid], sred[512 + 128 + tid]),
                         fmaxf(sred[512 + 256 + tid], sred[512 + 384 + tid]));
        float mn = fminf(fminf(sred[1024 + tid], sred[1024 + 128 + tid]),
                         fminf(sred[1024 + 256 + tid], sred[1024 + 384 + tid]));
        const int r = g * SEQ + i0 + tid;
        atomicAdd(&rsum[r], s);
        atomicMaxF(&rmaxp[r], mx);
        atomicMinF(&rminp[r], mn);
    }
}

__global__ void init_stats(float* rsum, float* rmax, float* rmin) {
    int i = blockIdx.x * blockDim.x + threadIdx.x;
    if (i < GH * SEQ) { rsum[i] = 0.f; rmax[i] = -FLT_MAX; rmin[i] = FLT_MAX; }
}

// ---------------- LayerNorm (1 block / row of 512) ----------------
__global__ void ln_kernel(const float* __restrict__ x, const float* __restrict__ w,
                          const float* __restrict__ b, float* __restrict__ y) {
    int row = blockIdx.x;
    const float* xr = x + (size_t)row * EMB;
    int t = threadIdx.x;
    float v0 = xr[t], v1 = xr[t + 256];
    float s = v0 + v1, q = v0 * v0 + v1 * v1;
#pragma unroll
    for (int off = 16; off; off >>= 1) {
        s += __shfl_xor_sync(~0u, s, off);
        q += __shfl_xor_sync(~0u, q, off);
    }
    __shared__ float ss[8], sq[8];
    if ((t & 31) == 0) { ss[t >> 5] = s; sq[t >> 5] = q; }
    __syncthreads();
    if (t == 0) {
        float s2 = 0.f, q2 = 0.f;
#pragma unroll
        for (int i = 0; i < 8; i++) { s2 += ss[i]; q2 += sq[i]; }
        ss[0] = s2; sq[0] = q2;
    }
    __syncthreads();
    float mean = ss[0] * (1.f / EMB);
    float var  = sq[0] * (1.f / EMB) - mean * mean;
    float rstd = rsqrtf(var + 1e-5f);
    float* yr = y + (size_t)row * EMB;
    yr[t]       = (v0 - mean) * rstd * w[t]       + b[t];
    yr[t + 256] = (v1 - mean) * rstd * w[t + 256] + b[t + 256];
}

// ======== fused: exp -> P fp16, Z, head-averaged attn weights (round-10) ========
#define AW_SMEM (8 * SEQ * 2)   // 32768 bytes of half
__global__ void sfmax_avg(const float* __restrict__ W, const float* __restrict__ rsum,
                          const float* __restrict__ rmaxp, const float* __restrict__ rminp,
                          __half* __restrict__ P, float* __restrict__ Z,
                          float* __restrict__ out) {
    extern __shared__ __half sph[];     // [8][2048] half
    __shared__ float sz[8];
    const int i = blockIdx.x, b = blockIdx.y;
    const int tid = threadIdx.x;
    if (tid < 8) sz[tid] = 0.f;
    __syncthreads();

    float inv[8], mh[8], z[8];
    int rowh[8];
#pragma unroll
    for (int h = 0; h < 8; h++) {
        rowh[h] = (b * 8 + h) * SEQ + i;
        float s = rsum[rowh[h]] + 1e-12f;
        inv[h] = 1.f / s;
        mh[h] = (s > 0.f) ? rmaxp[rowh[h]] * inv[h] : rminp[rowh[h]] * inv[h];
        z[h] = 0.f;
    }

#pragma unroll
    for (int k = 0; k < 2; k++) {
        const int j = (tid + (k << 8)) << 2;
        float4 w4[8];
#pragma unroll
        for (int h = 0; h < 8; h++)
            w4[h] = *(const float4*)&W[(size_t)rowh[h] * SEQ + j];
#pragma unroll
        for (int h = 0; h < 8; h++) {
            float4 p;
            p.x = __expf(fmaf(w4[h].x, inv[h], -mh[h]));
            p.y = __expf(fmaf(w4[h].y, inv[h], -mh[h]));
            p.z = __expf(fmaf(w4[h].z, inv[h], -mh[h]));
            p.w = __expf(fmaf(w4[h].w, inv[h], -mh[h]));
            __half2 h0 = __floats2half2_rn(p.x, p.y);
            __half2 h1 = __floats2half2_rn(p.z, p.w);
            uint2 pk = make_uint2(*(uint32_t*)&h0, *(uint32_t*)&h1);
            *(uint2*)&P[(size_t)rowh[h] * SEQ + j] = pk;
            *(uint2*)&sph[h * SEQ + j] = pk;
            z[h] += (p.x + p.y) + (p.z + p.w);
        }
    }
#pragma unroll
    for (int h = 0; h < 8; h++) {
#pragma unroll
        for (int off = 16; off; off >>= 1) z[h] += __shfl_xor_sync(~0u, z[h], off);
    }
    if ((tid & 31) == 0) {
#pragma unroll
        for (int h = 0; h < 8; h++) atomicAdd(&sz[h], z[h]);
    }
    __syncthreads();
    if (tid < 8) Z[(b * 8 + tid) * SEQ + i] = sz[tid];
    float iz[8];
#pragma unroll
    for (int h = 0; h < 8; h++) iz[h] = 0.125f / sz[h];
    float* orow = out + (size_t)b * SEQ * SEQ + (size_t)i * SEQ;
#pragma unroll
    for (int k = 0; k < 2; k++) {
        const int j = (tid + (k << 8)) << 2;
        float4 a = make_float4(0.f, 0.f, 0.f, 0.f);
#pragma unroll
        for (int h = 0; h < 8; h++) {
            uint2 pk = *(const uint2*)&sph[h * SEQ + j];
            float2 p01 = __half22float2(*(__half2*)&pk.x);
            float2 p23 = __half22float2(*(__half2*)&pk.y);
            a.x = fmaf(p01.x, iz[h], a.x);
            a.y = fmaf(p01.y, iz[h], a.y);
            a.z = fmaf(p23.x, iz[h], a.z);
            a.w = fmaf(p23.y, iz[h], a.w);
        }
        *(float4*)&orow[j] = a;
    }
}

// ======== PV via fp16 mma: Oc[(b,s),h*64+d] = (sum_k P[g,s,k] V[g,k,d]) / Z ========
#define PVS 40
__global__ __launch_bounds__(128, 4)
void pv_mma(const __half* __restrict__ P, const float* __restrict__ V,
            const float* __restrict__ Z, float* __restrict__ Oc) {
    __shared__ __half Ps[128 * PVS];
    __shared__ __half Vs[64 * PVS];
    const int g = blockIdx.y;
    const int m0 = blockIdx.x << 7;
    const int tid = threadIdx.x;
    const int wid = tid >> 5, lid = tid & 31;
    const int gq = lid >> 2, t4 = lid & 3;
    const int wm = wid << 5;

    const __half* Pg = P + (size_t)g * SEQ * SEQ;
    const float*  Vg = V + (size_t)g * SEQ * DH;

    float acc[2][8][4];
#pragma unroll
    for (int mi = 0; mi < 2; mi++)
#pragma unroll
        for (int ni = 0; ni < 8; ni++)
#pragma unroll
            for (int f = 0; f < 4; f++) acc[mi][ni][f] = 0.f;

    const int vk = tid >> 2;
    const int vc = (tid & 3) << 4;

    for (int k0 = 0; k0 < SEQ; k0 += 32) {
        const __half* prow = Pg + (size_t)(m0 + tid) * SEQ + k0;
        float4 p0 = *(const float4*)(prow + 0);
        float4 p1 = *(const float4*)(prow + 8);
        float4 p2 = *(const float4*)(prow + 16);
        float4 p3 = *(const float4*)(prow + 24);
        float4 v4[4];
#pragma unroll
        for (int i = 0; i < 4; i++)
            v4[i] = *(const float4*)&Vg[(size_t)(k0 + vk) * DH + vc + (i << 2)];
        __syncthreads();
        {
            __half* pd = &Ps[tid * PVS];
            *(float4*)(pd + 0)  = p0;
            *(float4*)(pd + 8)  = p1;
            *(float4*)(pd + 16) = p2;
            *(float4*)(pd + 24) = p3;
#pragma unroll
            for (int i = 0; i < 4; i++) {
                Vs[(vc + (i << 2) + 0) * PVS + vk] = __float2half_rn(v4[i].x);
                Vs[(vc + (i << 2) + 1) * PVS + vk] = __float2half_rn(v4[i].y);
                Vs[(vc + (i << 2) + 2) * PVS + vk] = __float2half_rn(v4[i].z);
                Vs[(vc + (i << 2) + 3) * PVS + vk] = __float2half_rn(v4[i].w);
            }
        }
        __syncthreads();
#pragma unroll
        for (int ks = 0; ks < 32; ks += 16) {
            uint32_t bf[8][2];
#pragma unroll
            for (int ni = 0; ni < 8; ni++) {
                const __half* vb = &Vs[((ni << 3) + gq) * PVS + ks];
                bf[ni][0] = *(const uint32_t*)(vb + (t4 << 1));
                bf[ni][1] = *(const uint32_t*)(vb + (t4 << 1) + 8);
            }
#pragma unroll
            for (int mi = 0; mi < 2; mi++) {
                const int r = wm + (mi << 4) + gq;
                const __half* pa0 = &Ps[r * PVS + ks];
                const __half* pa8 = &Ps[(r + 8) * PVS + ks];
                uint32_t af[4];
                af[0] = *(const uint32_t*)(pa0 + (t4 << 1));
                af[1] = *(const uint32_t*)(pa8 + (t4 << 1));
                af[2] = *(const uint32_t*)(pa0 + (t4 << 1) + 8);
                af[3] = *(const uint32_t*)(pa8 + (t4 << 1) + 8);
#pragma unroll
                for (int ni = 0; ni < 8; ni++)
                    mma16h(acc[mi][ni], af, bf[ni]);
            }
        }
    }

    const int b = g >> 3, h = g & 7;
    float* ocb = Oc + (size_t)b * SEQ * EMB + h * 64;
#pragma unroll
    for (int mi = 0; mi < 2; mi++) {
#pragma unroll
        for (int half = 0; half < 2; half++) {
            const int lrow = wm + (mi << 4) + gq + (half << 3);
            const float izv = 1.f / Z[g * SEQ + m0 + lrow];
            float* orow = ocb + (size_t)(m0 + lrow) * EMB;
#pragma unroll
            for (int ni = 0; ni < 8; ni++) {
                const int col = (ni << 3) + (t4 << 1);
                float2 o = make_float2(acc[mi][ni][half * 2 + 0] * izv,
                                       acc[mi][ni][half * 2 + 1] * izv);
                *(float2*)&orow[col] = o;
            }
        }
    }
}

// ---------------- launcher ----------------
extern "C" void kernel_launch(void* const* d_in, const int* in_sizes, int n_in,
                              void* d_out, int out_size) {
    const float* query = (const float*)d_in[0];
    const float* gate  = (const float*)d_in[1];
    const float* ipw   = (const float*)d_in[2];
    const float* ipb   = (const float*)d_in[3];
    const float* outw  = (const float*)d_in[4];
    const float* outb  = (const float*)d_in[5];
    const float* ln1w  = (const float*)d_in[6];
    const float* ln1b  = (const float*)d_in[7];
    const float* ln2w  = (const float*)d_in[8];
    const float* ln2b  = (const float*)d_in[9];
    const float* w1    = (const float*)d_in[10];
    const float* b1    = (const float*)d_in[11];
    const float* w2    = (const float*)d_in[12];
    const float* b2    = (const float*)d_in[13];
    float* out_x = (float*)d_out;
    float* out_w = out_x + (size_t)2 * SEQ * EMB;

    float *p_nq, *p_q, *p_k, *p_v, *p_W, *p_rsum, *p_rmax, *p_rmin, *p_Z;
    float *p_Oc, *p_x, *p_h, *p_mlp;
    __half* p_P;
    cudaGetSymbolAddress((void**)&p_nq,  g_nq);
    cudaGetSymbolAddress((void**)&p_q,   g_q);
    cudaGetSymbolAddress((void**)&p_k,   g_k);
    cudaGetSymbolAddress((void**)&p_v,   g_v);
    cudaGetSymbolAddress((void**)&p_W,   g_W);
    cudaGetSymbolAddress((void**)&p_P,   g_P);
    cudaGetSymbolAddress((void**)&p_rsum,g_rsum);
    cudaGetSymbolAddress((void**)&p_rmax,g_rmax);
    cudaGetSymbolAddress((void**)&p_rmin,g_rmin);
    cudaGetSymbolAddress((void**)&p_Z,   g_Z);
    cudaGetSymbolAddress((void**)&p_Oc,  g_Oc);
    cudaGetSymbolAddress((void**)&p_x,   g_x);
    cudaGetSymbolAddress((void**)&p_h,   g_h);
    cudaGetSymbolAddress((void**)&p_mlp, g_mlp);

    cudaFuncSetAttribute(sgemm_mma<0>, cudaFuncAttributeMaxDynamicSharedMemorySize, MM_SMEM);
    cudaFuncSetAttribute(sgemm_mma<1>, cudaFuncAttributeMaxDynamicSharedMemorySize, MM_SMEM);
    cudaFuncSetAttribute(sgemm_mma<2>, cudaFuncAttributeMaxDynamicSharedMemorySize, MM_SMEM);
    cudaFuncSetAttribute(scores_mma,   cudaFuncAttributeMaxDynamicSharedMemorySize, SC_SMEM);
    cudaFuncSetAttribute(sfmax_avg,    cudaFuncAttributeMaxDynamicSharedMemorySize, AW_SMEM);

    init_stats<<<(GH * SEQ + 255) / 256, 256>>>(p_rsum, p_rmax, p_rmin);
    ln_kernel<<<MR, 256>>>(query, ln1w, ln1b, p_nq);
    sgemm_mma<0><<<dim3(12, 32), 256, MM_SMEM>>>(p_nq, ipw, ipb, nullptr, p_q, p_k, p_v, 1536, EMB);
    scores_mma<<<dim3(16, 16, GH), 256, SC_SMEM>>>(p_q, p_k, gate, p_W, p_rsum, p_rmax, p_rmin);
    sfmax_avg<<<dim3(SEQ, 2), 256, AW_SMEM>>>(p_W, p_rsum, p_rmax, p_rmin, p_P, p_Z, out_w);
    pv_mma<<<dim3(16, GH), 128>>>(p_P, p_v, p_Z, p_Oc);
    sgemm_mma<1><<<dim3(4, 32), 256, MM_SMEM>>>(p_Oc, outw, outb, query, p_x, nullptr, nullptr, EMB, EMB);
    ln_kernel<<<MR, 256>>>(p_x, ln2w, ln2b, p_h);
    sgemm_mma<2><<<dim3(16, 32), 256, MM_SMEM>>>(p_h, w1, b1, nullptr, p_mlp, nullptr, nullptr, MLPD, EMB);
    sgemm_mma<1><<<dim3(4, 32), 256, MM_SMEM>>>(p_mlp, w2, b2, p_x, out_x, nullptr, nullptr, EMB, MLPD);
}

// round 14
// speedup vs baseline: 1.5767x; 1.0353x over previous
#include <cuda_runtime.h>
#include <cuda_fp16.h>
#include <cuda_bf16.h>
#include <math.h>
#include <float.h>
#include <stdint.h>

// Problem constants
#define GH   16        // B*H groups
#define SEQ  2048
#define EMB  512
#define DH   64
#define MR   4096      // B*S rows
#define MLPD 2048

typedef unsigned long long u64;

// ---------------- scratch (static device globals; no allocation) ----------------
__device__ float  g_nq [MR*EMB];
__device__ float  g_q  [MR*EMB];
__device__ float  g_k  [MR*EMB];
__device__ float  g_v  [MR*EMB];
__device__ float  g_W  [(size_t)GH*SEQ*SEQ];     // 256MB raw gated scores (fp32)
__device__ __half g_P  [(size_t)GH*SEQ*SEQ];     // 128MB exp'd (un-normalized) probs
__device__ float  g_rsum[GH*SEQ];
__device__ float  g_rmax[GH*SEQ];
__device__ float  g_rmin[GH*SEQ];
__device__ float  g_Z  [GH*SEQ];
__device__ float  g_Oc [MR*EMB];
__device__ float  g_x  [MR*EMB];
__device__ float  g_h  [MR*EMB];
__device__ float  g_mlp[(size_t)MR*MLPD];

// ---------------- misc helpers ----------------
__device__ __forceinline__ void atomicMaxF(float* addr, float val) {
    int old = __float_as_int(*addr);
    while (__int_as_float(old) < val) {
        int assumed = old;
        old = atomicCAS((int*)addr, assumed, __float_as_int(val));
        if (old == assumed) break;
    }
}
__device__ __forceinline__ void atomicMinF(float* addr, float val) {
    int old = __float_as_int(*addr);
    while (__int_as_float(old) > val) {
        int assumed = old;
        old = atomicCAS((int*)addr, assumed, __float_as_int(val));
        if (old == assumed) break;
    }
}

// ---------------- mma helpers ----------------
__device__ __forceinline__ void mmabf(float* c, const uint32_t* a, const uint32_t* b) {
    asm volatile(
        "mma.sync.aligned.m16n8k16.row.col.f32.bf16.bf16.f32 "
        "{%0,%1,%2,%3}, {%4,%5,%6,%7}, {%8,%9}, {%0,%1,%2,%3};"
        : "+f"(c[0]), "+f"(c[1]), "+f"(c[2]), "+f"(c[3])
        : "r"(a[0]), "r"(a[1]), "r"(a[2]), "r"(a[3]), "r"(b[0]), "r"(b[1]));
}
__device__ __forceinline__ void mma16h(float* c, const uint32_t* a, const uint32_t* b) {
    asm volatile(
        "mma.sync.aligned.m16n8k16.row.col.f32.f16.f16.f32 "
        "{%0,%1,%2,%3}, {%4,%5,%6,%7}, {%8,%9}, {%0,%1,%2,%3};"
        : "+f"(c[0]), "+f"(c[1]), "+f"(c[2]), "+f"(c[3])
        : "r"(a[0]), "r"(a[1]), "r"(a[2]), "r"(a[3]), "r"(b[0]), "r"(b[1]));
}

// split two consecutive fp32 values into packed bf16 (hi,hi) and (lo,lo) pairs
__device__ __forceinline__ void bfsplit2(float x, float y, uint32_t& h, uint32_t& l) {
    __nv_bfloat16 hx = __float2bfloat16_rn(x);
    __nv_bfloat16 hy = __float2bfloat16_rn(y);
    float lx = x - __bfloat162float(hx);
    float ly = y - __bfloat162float(hy);
    __nv_bfloat162 hp = __halves2bfloat162(hx, hy);
    __nv_bfloat162 lp = __halves2bfloat162(__float2bfloat16_rn(lx), __float2bfloat16_rn(ly));
    h = *(uint32_t*)&hp;
    l = *(uint32_t*)&lp;
}

// ---------------- bf16-pair smem layout ----------------
// per matrix: 128 rows x 20 uint32 (32 bf16 k-values + pad); row stride 80B.
#define RSTR   20                       // uint32 per row
#define MATU   (128 * RSTR)             // 2560 uint32 per matrix
#define STAGEU (4 * MATU)               // Ah, Al, Bh, Bl for one buffer
#define MM_SMEM (2 * STAGEU * 4)        // double-buffered: 81920 bytes
#define SC_SMEM (STAGEU * 4)            // scores: single buffer, 40960 bytes

// one K=32 chunk = 2 k16 steps of 3xBF16 mma (shared by dense + scores)
__device__ __forceinline__ void mma_chunk_bf(const uint32_t* sAh, const uint32_t* sAl,
                                             const uint32_t* sBh, const uint32_t* sBl,
                                             int wm, int wn, int g, int t4,
                                             float (&acc)[4][4][4]) {
#pragma unroll
    for (int ks = 0; ks < 2; ks++) {
        const int kq = (ks << 3) + t4;
        uint32_t bh[4][2], bl[4][2];
#pragma unroll
        for (int ni = 0; ni < 4; ni++) {
            const int nn = (wn + (ni << 3) + g) * RSTR + kq;
            bh[ni][0] = sBh[nn]; bh[ni][1] = sBh[nn + 4];
            bl[ni][0] = sBl[nn]; bl[ni][1] = sBl[nn + 4];
        }
#pragma unroll
        for (int mi = 0; mi < 4; mi++) {
            const int r0 = (wm + (mi << 4) + g) * RSTR + kq;
            const int r8 = r0 + (RSTR << 3);
            uint32_t ah[4] = { sAh[r0], sAh[r8], sAh[r0 + 4], sAh[r8 + 4] };
            uint32_t al[4] = { sAl[r0], sAl[r8], sAl[r0 + 4], sAl[r8 + 4] };
#pragma unroll
            for (int ni = 0; ni < 4; ni++) {
                mmabf(acc[mi][ni], ah, bh[ni]);
                mmabf(acc[mi][ni], ah, bl[ni]);
                mmabf(acc[mi][ni], al, bh[ni]);
            }
        }
    }
}

// convert 16 raw floats (4 float4) to hi/lo packed pairs and store (2 x uint4 each)
__device__ __forceinline__ void split_store_bf(uint32_t* dstH, uint32_t* dstL,
                                               int base32, const float4* r) {
    uint32_t h[8], l[8];
#pragma unroll
    for (int i = 0; i < 4; i++) {
        bfsplit2(r[i].x, r[i].y, h[i * 2 + 0], l[i * 2 + 0]);
        bfsplit2(r[i].z, r[i].w, h[i * 2 + 1], l[i * 2 + 1]);
    }
    *(uint4*)&dstH[base32]     = make_uint4(h[0], h[1], h[2], h[3]);
    *(uint4*)&dstH[base32 + 4] = make_uint4(h[4], h[5], h[6], h[7]);
    *(uint4*)&dstL[base32]     = make_uint4(l[0], l[1], l[2], l[3]);
    *(uint4*)&dstL[base32 + 4] = make_uint4(l[4], l[5], l[6], l[7]);
}

// ======== dense GEMM (3xBF16, double-buffered): C[m,n]=sum_k A[m,k]B[n,k]+bias ====
// Block 128x128, 8 warps (2m x 4n), warp tile 64x32. K chunks of 32.
// EPI 0: qkv split; 1: +residual; 2: exact gelu.
template <int EPI>
__global__ __launch_bounds__(256, 2)
void sgemm_mma(const float* __restrict__ A, const float* __restrict__ B,
               const float* __restrict__ bias, const float* __restrict__ res,
               float* __restrict__ C0, float* __restrict__ C1, float* __restrict__ C2,
               int N, int K) {
    extern __shared__ uint32_t su[];

    const int tid = threadIdx.x;
    const int wid = tid >> 5, lid = tid & 31;
    const int g = lid >> 2, t4 = lid & 3;
    const int wm = (wid >> 2) << 6;
    const int wn = (wid & 3) << 5;
    const int m0 = blockIdx.y << 7, n0 = blockIdx.x << 7;
    const int nc = K >> 5;

    const int lrow = tid >> 1;
    const int lkb  = (tid & 1) << 4;
    const int base32 = lrow * RSTR + ((tid & 1) << 3);
    const float* Arow = A + (size_t)(m0 + lrow) * K + lkb;
    const float* Brow = B + (size_t)(n0 + lrow) * K + lkb;

    float4 ra[4], rb[4];
    auto load_regs = [&](int c) {
        const int kc = c << 5;
#pragma unroll
        for (int i = 0; i < 4; i++) {
            ra[i] = *(const float4*)(Arow + kc + (i << 2));
            rb[i] = *(const float4*)(Brow + kc + (i << 2));
        }
    };
    auto store_buf = [&](int buf) {
        uint32_t* b0 = su + buf * STAGEU;
        split_store_bf(b0, b0 + MATU, base32, ra);
        split_store_bf(b0 + 2 * MATU, b0 + 3 * MATU, base32, rb);
    };

    float acc[4][4][4];
#pragma unroll
    for (int mi = 0; mi < 4; mi++)
#pragma unroll
        for (int ni = 0; ni < 4; ni++)
#pragma unroll
            for (int f = 0; f < 4; f++) acc[mi][ni][f] = 0.f;

    load_regs(0);
    store_buf(0);
    __syncthreads();

    for (int c = 0; c < nc; c++) {
        const int cur = c & 1;
        if (c + 1 < nc) {
            load_regs(c + 1);
            store_buf(cur ^ 1);          // idle buffer; prior readers synced at c-1
        }
        uint32_t* b0 = su + cur * STAGEU;
        mma_chunk_bf(b0, b0 + MATU, b0 + 2 * MATU, b0 + 3 * MATU, wm, wn, g, t4, acc);
        __syncthreads();
    }

    auto epi2 = [&](int row, int col, float v0, float v1) {
        v0 += bias[col]; v1 += bias[col + 1];
        if (EPI == 0) {
            float* dst = (col < 512) ? C0 : ((col < 1024) ? C1 : C2);
            *(float2*)&dst[(size_t)row * 512 + (col & 511)] = make_float2(v0, v1);
        } else if (EPI == 1) {
            float2 rv = *(const float2*)&res[(size_t)row * N + col];
            *(float2*)&C0[(size_t)row * N + col] = make_float2(v0 + rv.x, v1 + rv.y);
        } else {
            float2 o;
            o.x = 0.5f * v0 * (1.f + erff(v0 * 0.7071067811865475f));
            o.y = 0.5f * v1 * (1.f + erff(v1 * 0.7071067811865475f));
            *(float2*)&C0[(size_t)row * N + col] = o;
        }
    };
#pragma unroll
    for (int mi = 0; mi < 4; mi++) {
        const int r = m0 + wm + (mi << 4) + g;
#pragma unroll
        for (int ni = 0; ni < 4; ni++) {
            const int cn = n0 + wn + (ni << 3) + (t4 << 1);
            epi2(r,     cn, acc[mi][ni][0], acc[mi][ni][1]);
            epi2(r + 8, cn, acc[mi][ni][2], acc[mi][ni][3]);
        }
    }
}

// ======== scores (3xBF16 mainloop, round-13): W = (Q K^T)*gate + stats ====
__global__ __launch_bounds__(256, 2)
void scores_mma(const float* __restrict__ Q, const float* __restrict__ Km,
                const float* __restrict__ gate, float* __restrict__ W,
                float* __restrict__ rsum, float* __restrict__ rmaxp,
                float* __restrict__ rminp) {
    extern __shared__ uint32_t su[];
    uint32_t* sAh = su;
    uint32_t* sAl = su + 1 * MATU;
    uint32_t* sBh = su + 2 * MATU;
    uint32_t* sBl = su + 3 * MATU;

    const int g = blockIdx.z;
    const int tid = threadIdx.x;
    const int wid = tid >> 5, lid = tid & 31;
    const int gq = lid >> 2, t4 = lid & 3;
    const int wm = (wid >> 2) << 6;
    const int wn = (wid & 3) << 5;
    const int i0 = blockIdx.y << 7, j0 = blockIdx.x << 7;

    const int lrow = tid >> 1;
    const int lkb  = (tid & 1) << 4;
    const int base32 = lrow * RSTR + ((tid & 1) << 3);
    const float* Arow = Q + (size_t)g * SEQ * DH + (size_t)(i0 + lrow) * DH + lkb;
    const float* Brow = Km + (size_t)g * SEQ * DH + (size_t)(j0 + lrow) * DH + lkb;

    float acc[4][4][4];
#pragma unroll
    for (int mi = 0; mi < 4; mi++)
#pragma unroll
        for (int ni = 0; ni < 4; ni++)
#pragma unroll
            for (int f = 0; f < 4; f++) acc[mi][ni][f] = 0.f;

#pragma unroll
    for (int c = 0; c < 2; c++) {
        float4 ra[4], rb[4];
        const int kc = c << 5;
#pragma unroll
        for (int i = 0; i < 4; i++) {
            ra[i] = *(const float4*)(Arow + kc + (i << 2));
            rb[i] = *(const float4*)(Brow + kc + (i << 2));
        }
        if (c) __syncthreads();
        split_store_bf(sAh, sAl, base32, ra);
        split_store_bf(sBh, sBl, base32, rb);
        __syncthreads();
        mma_chunk_bf(sAh, sAl, sBh, sBl, wm, wn, gq, t4, acc);
    }

    // ---- epilogue (round-6/10 structure): gate mult, W store, stats ----
    __syncthreads();
    float* sred = (float*)su;           // [3][4][128]
    const size_t wb = (size_t)g * SEQ * SEQ;

#pragma unroll
    for (int mi = 0; mi < 4; mi++) {
#pragma unroll
        for (int half = 0; half < 2; half++) {
            const int row = wm + (mi << 4) + gq + (half << 3);
            const int grow = i0 + row;
            float s = 0.f, mx = -FLT_MAX, mn = FLT_MAX;
#pragma unroll
            for (int ni = 0; ni < 4; ni++) {
                const int cn = j0 + wn + (ni << 3) + (t4 << 1);
                const size_t off = wb + (size_t)grow * SEQ + cn;
                float2 gt = *(const float2*)&gate[off];
                float v0 = acc[mi][ni][half * 2 + 0] * gt.x;
                float v1 = acc[mi][ni][half * 2 + 1] * gt.y;
                *(float2*)&W[off] = make_float2(v0, v1);
                s += v0 + v1;
                mx = fmaxf(mx, fmaxf(v0, v1));
                mn = fminf(mn, fminf(v0, v1));
            }
#pragma unroll
            for (int o = 1; o < 4; o <<= 1) {
                s += __shfl_xor_sync(~0u, s, o);
                mx = fmaxf(mx, __shfl_xor_sync(~0u, mx, o));
                mn = fminf(mn, __shfl_xor_sync(~0u, mn, o));
            }
            if (t4 == 0) {
                const int wi = wid & 3;
                sred[0 * 512 + wi * 128 + row] = s;
                sred[1 * 512 + wi * 128 + row] = mx;
                sred[2 * 512 + wi * 128 + row] = mn;
            }
        }
    }
    __syncthreads();
    if (tid < 128) {
        float s  = sred[tid] + sred[128 + tid] + sred[256 + tid] + sred[384 + tid];
        float mx = fmaxf(fmaxf(sred[512 + tid], sred[512 + 128 + tid]),
                         fmaxf(sred[512 + 256 + tid], sred[512 + 384 + tid]));
        float mn = fminf(fminf(sred[1024 + tid], sred[1024 + 128 + tid]),
                         fminf(sred[1024 + 256 + tid], sred[1024 + 384 + tid]));
        const int r = g * SEQ + i0 + tid;
        atomicAdd(&rsum[r], s);
        atomicMaxF(&rmaxp[r], mx);
        atomicMinF(&rminp[r], mn);
    }
}

__global__ void init_stats(float* rsum, float* rmax, float* rmin) {
    int i = blockIdx.x * blockDim.x + threadIdx.x;
    if (i < GH * SEQ) { rsum[i] = 0.f; rmax[i] = -FLT_MAX; rmin[i] = FLT_MAX; }
}

// ---------------- LayerNorm (1 block / row of 512) ----------------
__global__ void ln_kernel(const float* __restrict__ x, const float* __restrict__ w,
                          const float* __restrict__ b, float* __restrict__ y) {
    int row = blockIdx.x;
    const float* xr = x + (size_t)row * EMB;
    int t = threadIdx.x;
    float v0 = xr[t], v1 = xr[t + 256];
    float s = v0 + v1, q = v0 * v0 + v1 * v1;
#pragma unroll
    for (int off = 16; off; off >>= 1) {
        s += __shfl_xor_sync(~0u, s, off);
        q += __shfl_xor_sync(~0u, q, off);
    }
    __shared__ float ss[8], sq[8];
    if ((t & 31) == 0) { ss[t >> 5] = s; sq[t >> 5] = q; }
    __syncthreads();
    if (t == 0) {
        float s2 = 0.f, q2 = 0.f;
#pragma unroll
        for (int i = 0; i < 8; i++) { s2 += ss[i]; q2 += sq[i]; }
        ss[0] = s2; sq[0] = q2;
    }
    __syncthreads();
    float mean = ss[0] * (1.f / EMB);
    float var  = sq[0] * (1.f / EMB) - mean * mean;
    float rstd = rsqrtf(var + 1e-5f);
    float* yr = y + (size_t)row * EMB;
    yr[t]       = (v0 - mean) * rstd * w[t]       + b[t];
    yr[t + 256] = (v1 - mean) * rstd * w[t + 256] + b[t + 256];
}

// ======== fused: exp -> P fp16, Z, head-averaged attn weights (round-10) ========
#define AW_SMEM (8 * SEQ * 2)   // 32768 bytes of half
__global__ void sfmax_avg(const float* __restrict__ W, const float* __restrict__ rsum,
                          const float* __restrict__ rmaxp, const float* __restrict__ rminp,
                          __half* __restrict__ P, float* __restrict__ Z,
                          float* __restrict__ out) {
    extern __shared__ __half sph[];     // [8][2048] half
    __shared__ float sz[8];
    const int i = blockIdx.x, b = blockIdx.y;
    const int tid = threadIdx.x;
    if (tid < 8) sz[tid] = 0.f;
    __syncthreads();

    float inv[8], mh[8], z[8];
    int rowh[8];
#pragma unroll
    for (int h = 0; h < 8; h++) {
        rowh[h] = (b * 8 + h) * SEQ + i;
        float s = rsum[rowh[h]] + 1e-12f;
        inv[h] = 1.f / s;
        mh[h] = (s > 0.f) ? rmaxp[rowh[h]] * inv[h] : rminp[rowh[h]] * inv[h];
        z[h] = 0.f;
    }

#pragma unroll
    for (int k = 0; k < 2; k++) {
        const int j = (tid + (k << 8)) << 2;
        float4 w4[8];
#pragma unroll
        for (int h = 0; h < 8; h++)
            w4[h] = *(const float4*)&W[(size_t)rowh[h] * SEQ + j];
#pragma unroll
        for (int h = 0; h < 8; h++) {
            float4 p;
            p.x = __expf(fmaf(w4[h].x, inv[h], -mh[h]));
            p.y = __expf(fmaf(w4[h].y, inv[h], -mh[h]));
            p.z = __expf(fmaf(w4[h].z, inv[h], -mh[h]));
            p.w = __expf(fmaf(w4[h].w, inv[h], -mh[h]));
            __half2 h0 = __floats2half2_rn(p.x, p.y);
            __half2 h1 = __floats2half2_rn(p.z, p.w);
            uint2 pk = make_uint2(*(uint32_t*)&h0, *(uint32_t*)&h1);
            *(uint2*)&P[(size_t)rowh[h] * SEQ + j] = pk;
            *(uint2*)&sph[h * SEQ + j] = pk;
            z[h] += (p.x + p.y) + (p.z + p.w);
        }
    }
#pragma unroll
    for (int h = 0; h < 8; h++) {
#pragma unroll
        for (int off = 16; off; off >>= 1) z[h] += __shfl_xor_sync(~0u, z[h], off);
    }
    if ((tid & 31) == 0) {
#pragma unroll
        for (int h = 0; h < 8; h++) atomicAdd(&sz[h], z[h]);
    }
    __syncthreads();
    if (tid < 8) Z[(b * 8 + tid) * SEQ + i] = sz[tid];
    float iz[8];
#pragma unroll
    for (int h = 0; h < 8; h++) iz[h] = 0.125f / sz[h];
    float* orow = out + (size_t)b * SEQ * SEQ + (size_t)i * SEQ;
#pragma unroll
    for (int k = 0; k < 2; k++) {
        const int j = (tid + (k << 8)) << 2;
        float4 a = make_float4(0.f, 0.f, 0.f, 0.f);
#pragma unroll
        for (int h = 0; h < 8; h++) {
            uint2 pk = *(const uint2*)&sph[h * SEQ + j];
            float2 p01 = __half22float2(*(__half2*)&pk.x);
            float2 p23 = __half22float2(*(__half2*)&pk.y);
            a.x = fmaf(p01.x, iz[h], a.x);
            a.y = fmaf(p01.y, iz[h], a.y);
            a.z = fmaf(p23.x, iz[h], a.z);
            a.w = fmaf(p23.y, iz[h], a.w);
        }
        *(float4*)&orow[j] = a;
    }
}

// ======== PV via fp16 mma: Oc[(b,s),h*64+d] = (sum_k P[g,s,k] V[g,k,d]) / Z ========
#define PVS 40
__global__ __launch_bounds__(128, 4)
void pv_mma(const __half* __restrict__ P, const float* __restrict__ V,
            const float* __restrict__ Z, float* __restrict__ Oc) {
    __shared__ __half Ps[128 * PVS];
    __shared__ __half Vs[64 * PVS];
    const int g = blockIdx.y;
    const int m0 = blockIdx.x << 7;
    const int tid = threadIdx.x;
    const int wid = tid >> 5, lid = tid & 31;
    const int gq = lid >> 2, t4 = lid & 3;
    const int wm = wid << 5;

    const __half* Pg = P + (size_t)g * SEQ * SEQ;
    const float*  Vg = V + (size_t)g * SEQ * DH;

    float acc[2][8][4];
#pragma unroll
    for (int mi = 0; mi < 2; mi++)
#pragma unroll
        for (int ni = 0; ni < 8; ni++)
#pragma unroll
            for (int f = 0; f < 4; f++) acc[mi][ni][f] = 0.f;

    const int vk = tid >> 2;
    const int vc = (tid & 3) << 4;

    for (int k0 = 0; k0 < SEQ; k0 += 32) {
        const __half* prow = Pg + (size_t)(m0 + tid) * SEQ + k0;
        float4 p0 = *(const float4*)(prow + 0);
        float4 p1 = *(const float4*)(prow + 8);
        float4 p2 = *(const float4*)(prow + 16);
        float4 p3 = *(const float4*)(prow + 24);
        float4 v4[4];
#pragma unroll
        for (int i = 0; i < 4; i++)
            v4[i] = *(const float4*)&Vg[(size_t)(k0 + vk) * DH + vc + (i << 2)];
        __syncthreads();
        {
            __half* pd = &Ps[tid * PVS];
            *(float4*)(pd + 0)  = p0;
            *(float4*)(pd + 8)  = p1;
            *(float4*)(pd + 16) = p2;
            *(float4*)(pd + 24) = p3;
#pragma unroll
            for (int i = 0; i < 4; i++) {
                Vs[(vc + (i << 2) + 0) * PVS + vk] = __float2half_rn(v4[i].x);
                Vs[(vc + (i << 2) + 1) * PVS + vk] = __float2half_rn(v4[i].y);
                Vs[(vc + (i << 2) + 2) * PVS + vk] = __float2half_rn(v4[i].z);
                Vs[(vc + (i << 2) + 3) * PVS + vk] = __float2half_rn(v4[i].w);
            }
        }
        __syncthreads();
#pragma unroll
        for (int ks = 0; ks < 32; ks += 16) {
            uint32_t bf[8][2];
#pragma unroll
            for (int ni = 0; ni < 8; ni++) {
                const __half* vb = &Vs[((ni << 3) + gq) * PVS + ks];
                bf[ni][0] = *(const uint32_t*)(vb + (t4 << 1));
                bf[ni][1] = *(const uint32_t*)(vb + (t4 << 1) + 8);
            }
#pragma unroll
            for (int mi = 0; mi < 2; mi++) {
                const int r = wm + (mi << 4) + gq;
                const __half* pa0 = &Ps[r * PVS + ks];
                const __half* pa8 = &Ps[(r + 8) * PVS + ks];
                uint32_t af[4];
                af[0] = *(const uint32_t*)(pa0 + (t4 << 1));
                af[1] = *(const uint32_t*)(pa8 + (t4 << 1));
                af[2] = *(const uint32_t*)(pa0 + (t4 << 1) + 8);
                af[3] = *(const uint32_t*)(pa8 + (t4 << 1) + 8);
#pragma unroll
                for (int ni = 0; ni < 8; ni++)
                    mma16h(acc[mi][ni], af, bf[ni]);
            }
        }
    }

    const int b = g >> 3, h = g & 7;
    float* ocb = Oc + (size_t)b * SEQ * EMB + h * 64;
#pragma unroll
    for (int mi = 0; mi < 2; mi++) {
#pragma unroll
        for (int half = 0; half < 2; half++) {
            const int lrow = wm + (mi << 4) + gq + (half << 3);
            const float izv = 1.f / Z[g * SEQ + m0 + lrow];
            float* orow = ocb + (size_t)(m0 + lrow) * EMB;
#pragma unroll
            for (int ni = 0; ni < 8; ni++) {
                const int col = (ni << 3) + (t4 << 1);
                float2 o = make_float2(acc[mi][ni][half * 2 + 0] * izv,
                                       acc[mi][ni][half * 2 + 1] * izv);
                *(float2*)&orow[col] = o;
            }
        }
    }
}

// ---------------- launcher ----------------
extern "C" void kernel_launch(void* const* d_in, const int* in_sizes, int n_in,
                              void* d_out, int out_size) {
    const float* query = (const float*)d_in[0];
    const float* gate  = (const float*)d_in[1];
    const float* ipw   = (const float*)d_in[2];
    const float* ipb   = (const float*)d_in[3];
    const float* outw  = (const float*)d_in[4];
    const float* outb  = (const float*)d_in[5];
    const float* ln1w  = (const float*)d_in[6];
    const float* ln1b  = (const float*)d_in[7];
    const float* ln2w  = (const float*)d_in[8];
    const float* ln2b  = (const float*)d_in[9];
    const float* w1    = (const float*)d_in[10];
    const float* b1    = (const float*)d_in[11];
    const float* w2    = (const float*)d_in[12];
    const float* b2    = (const float*)d_in[13];
    float* out_x = (float*)d_out;
    float* out_w = out_x + (size_t)2 * SEQ * EMB;

    float *p_nq, *p_q, *p_k, *p_v, *p_W, *p_rsum, *p_rmax, *p_rmin, *p_Z;
    float *p_Oc, *p_x, *p_h, *p_mlp;
    __half* p_P;
    cudaGetSymbolAddress((void**)&p_nq,  g_nq);
    cudaGetSymbolAddress((void**)&p_q,   g_q);
    cudaGetSymbolAddress((void**)&p_k,   g_k);
    cudaGetSymbolAddress((void**)&p_v,   g_v);
    cudaGetSymbolAddress((void**)&p_W,   g_W);
    cudaGetSymbolAddress((void**)&p_P,   g_P);
    cudaGetSymbolAddress((void**)&p_rsum,g_rsum);
    cudaGetSymbolAddress((void**)&p_rmax,g_rmax);
    cudaGetSymbolAddress((void**)&p_rmin,g_rmin);
    cudaGetSymbolAddress((void**)&p_Z,   g_Z);
    cudaGetSymbolAddress((void**)&p_Oc,  g_Oc);
    cudaGetSymbolAddress((void**)&p_x,   g_x);
    cudaGetSymbolAddress((void**)&p_h,   g_h);
    cudaGetSymbolAddress((void**)&p_mlp, g_mlp);

    cudaFuncSetAttribute(sgemm_mma<0>, cudaFuncAttributeMaxDynamicSharedMemorySize, MM_SMEM);
    cudaFuncSetAttribute(sgemm_mma<1>, cudaFuncAttributeMaxDynamicSharedMemorySize, MM_SMEM);
    cudaFuncSetAttribute(sgemm_mma<2>, cudaFuncAttributeMaxDynamicSharedMemorySize, MM_SMEM);
    cudaFuncSetAttribute(scores_mma,   cudaFuncAttributeMaxDynamicSharedMemorySize, SC_SMEM);
    cudaFuncSetAttribute(sfmax_avg,    cudaFuncAttributeMaxDynamicSharedMemorySize, AW_SMEM);

    init_stats<<<(GH * SEQ + 255) / 256, 256>>>(p_rsum, p_rmax, p_rmin);
    ln_kernel<<<MR, 256>>>(query, ln1w, ln1b, p_nq);
    sgemm_mma<0><<<dim3(12, 32), 256, MM_SMEM>>>(p_nq, ipw, ipb, nullptr, p_q, p_k, p_v, 1536, EMB);
    scores_mma<<<dim3(16, 16, GH), 256, SC_SMEM>>>(p_q, p_k, gate, p_W, p_rsum, p_rmax, p_rmin);
    sfmax_avg<<<dim3(SEQ, 2), 256, AW_SMEM>>>(p_W, p_rsum, p_rmax, p_rmin, p_P, p_Z, out_w);
    pv_mma<<<dim3(16, GH), 128>>>(p_P, p_v, p_Z, p_Oc);
    sgemm_mma<1><<<dim3(4, 32), 256, MM_SMEM>>>(p_Oc, outw, outb, query, p_x, nullptr, nullptr, EMB, EMB);
    ln_kernel<<<MR, 256>>>(p_x, ln2w, ln2b, p_h);
    sgemm_mma<2><<<dim3(16, 32), 256, MM_SMEM>>>(p_h, w1, b1, nullptr, p_mlp, nullptr, nullptr, MLPD, EMB);
    sgemm_mma<1><<<dim3(4, 32), 256, MM_SMEM>>>(p_mlp, w2, b2, p_x, out_x, nullptr, nullptr, EMB, MLPD);
}